// round 14
// baseline (speedup 1.0000x reference)
#include <cuda_runtime.h>
#include <math.h>
#include <stdint.h>

// ---------------------------------------------------------------------------
// Problem constants
// ---------------------------------------------------------------------------
constexpr int Bc = 64, Hc = 128, Wc = 128, PSc = 8, Gc = 16, Ec = 256;
constexpr int NSc = 8, ITc = 3, Vc = 10, FDc = 320, HEADSc = 4, HDc = 64;
constexpr int Nc = Gc * Gc;          // 256 tokens per image
constexpr int TOK = Bc * Nc;         // 16384 rows

// ---------------------------------------------------------------------------
// Device scratch
// ---------------------------------------------------------------------------
__device__ float g_P   [TOK * 768];        // im2col patches; reused for QKV
__device__ float g_x0  [TOK * Ec];
__device__ float g_ln  [TOK * Ec];
__device__ float g_h1  [TOK * 512];
__device__ float g_x2  [TOK * Ec];
__device__ float g_ao  [TOK * Ec];
__device__ float g_x3  [TOK * Ec];
__device__ float g_cosT[Nc * HDc];
__device__ float g_sinT[Nc * HDc];
// slot path (collapsed: one row per batch, slots identical across s)
__device__ float g_xbar [Bc * Ec];
__device__ float g_vbar [Bc * FDc];
__device__ float g_slots[Bc * FDc];
__device__ float g_sln  [Bc * FDc];
__device__ float g_gi   [Bc * 3 * FDc];
__device__ float g_gh   [Bc * 3 * FDc];
__device__ float g_m1   [Bc * 2 * FDc];

// ---------------------------------------------------------------------------
// Helpers
// ---------------------------------------------------------------------------
__device__ __forceinline__ float gelu_exact(float x) {
    return 0.5f * x * (1.0f + erff(x * 0.70710678118654752f));
}

__device__ __forceinline__ uint32_t f2tf32(float x) {
    uint32_t r;
    asm("cvt.rna.tf32.f32 %0, %1;" : "=r"(r) : "f"(x));
    return r;
}

__device__ __forceinline__ void mma_tf32(float (&d)[4], const uint32_t (&a)[4],
                                         const uint32_t (&b)[2]) {
    asm volatile(
        "mma.sync.aligned.m16n8k8.row.col.f32.tf32.tf32.f32 "
        "{%0,%1,%2,%3}, {%4,%5,%6,%7}, {%8,%9}, {%0,%1,%2,%3};\n"
        : "+f"(d[0]), "+f"(d[1]), "+f"(d[2]), "+f"(d[3])
        : "r"(a[0]), "r"(a[1]), "r"(a[2]), "r"(a[3]), "r"(b[0]), "r"(b[1]));
}

__device__ __forceinline__ uint32_t smem_u32(const void* p) {
    return (uint32_t)__cvta_generic_to_shared(p);
}

__device__ __forceinline__ void cp_async16(uint32_t dst, const void* src) {
    asm volatile("cp.async.ca.shared.global [%0], [%1], 16;\n"
                 :: "r"(dst), "l"(src));
}

__device__ __forceinline__ void cp_commit() {
    asm volatile("cp.async.commit_group;\n");
}

template <int N>
__device__ __forceinline__ void cp_wait() {
    asm volatile("cp.async.wait_group %0;\n" :: "n"(N));
}

// ---------------------------------------------------------------------------
// RoPE tables
// ---------------------------------------------------------------------------
__global__ void rope_init_kernel() {
    int n = blockIdx.x;          // 0..255
    int d = threadIdx.x;         // 0..63
    int gy = n >> 4, gx = n & 15;
    int pos = (d < 32) ? gy : gx;
    int dd  = (d < 32) ? d : d - 32;
    float val;
    if (dd < 16) {
        float inv = expf(-9.210340371976184f * (2.0f * dd) / 32.0f);
        val = sinf((float)pos * inv);
    } else {
        float inv = expf(-9.210340371976184f * (2.0f * (dd - 16)) / 32.0f);
        val = cosf((float)pos * inv);
    }
    g_cosT[n * 64 + d] = cosf(val);
    g_sinT[n * 64 + d] = sinf(val);
}

// ---------------------------------------------------------------------------
// Patch / im2col builder: 4 tokens per 256-thread block.
// ---------------------------------------------------------------------------
__global__ __launch_bounds__(256)
void patch_kernel(const float* __restrict__ state, float* __restrict__ P) {
    int bn = blockIdx.x * 4 + (threadIdx.x >> 6);
    int b = bn >> 8, n = bn & 255;
    int gy = n >> 4, gx = n & 15;
    int p = threadIdx.x & 63;          // 0..63
    int py = p >> 3, px = p & 7;
    int y = gy * 8 + py, x = gx * 8 + px;
    const float* sb = state + (size_t)b * Hc * Wc;
    float* row = P + (size_t)bn * 768;
    for (int k = p; k < 768; k += 64) row[k] = 0.f;

    float v[3][3];
    #pragma unroll
    for (int di = 0; di < 3; di++) {
        int yy = min(max(y + di - 1, 0), Hc - 1);
        #pragma unroll
        for (int dj = 0; dj < 3; dj++) {
            int xx = min(max(x + dj - 1, 0), Wc - 1);
            v[di][dj] = sb[yy * Wc + xx];
        }
    }
    float sx = (v[0][2] + 2.f * v[1][2] + v[2][2]) - (v[0][0] + 2.f * v[1][0] + v[2][0]);
    float sy = (v[2][0] + 2.f * v[2][1] + v[2][2]) - (v[0][0] + 2.f * v[0][1] + v[0][2]);
    int id = (int)sb[y * Wc + x];
    __syncthreads();
    row[id * 64 + p]  = 1.f;
    row[640 + p]      = sx;
    row[704 + p]      = sy;
}

// ---------------------------------------------------------------------------
// TF32 tensor-core GEMM with cp.async double-buffered mainloop.
// BM=128, BN=64, BK=16, 256 threads (8 warps), warp tile m32 x n32.
// Smaller warp tile (acc 32 regs) -> 3 CTAs/SM for latency hiding.
// Per-output K-accumulation order identical to previous versions.
// ---------------------------------------------------------------------------
__global__ __launch_bounds__(256, 3)
void gemm128_kernel(const float* __restrict__ A,
                    const float* __restrict__ W,
                    const float* __restrict__ bias, const float* __restrict__ res,
                    float* __restrict__ C,
                    int M, int N, int K, int act) {
    __shared__ float As[2][128][20];
    __shared__ float Bs[2][64][20];

    int tid = threadIdx.x;
    int m0 = blockIdx.y * 128, n0 = blockIdx.x * 64;
    int warp = tid >> 5, lane = tid & 31;
    int wm = warp & 3, wn = warp >> 2;   // wm: 4 x 32 rows, wn: 2 x 32 cols
    int q = lane >> 2, t = lane & 3;

    int r  = tid >> 2;                   // 0..63
    int k4 = (tid & 3) << 2;             // 0,4,8,12

    const float* Ap0 = A + (size_t)(m0 + r) * K + k4;
    const float* Ap1 = Ap0 + (size_t)64 * K;
    const float* Wp0 = W + (size_t)(n0 + r) * K + k4;

    uint32_t dA0[2], dA1[2], dB0[2];
    #pragma unroll
    for (int s = 0; s < 2; s++) {
        dA0[s] = smem_u32(&As[s][r][k4]);
        dA1[s] = smem_u32(&As[s][r + 64][k4]);
        dB0[s] = smem_u32(&Bs[s][r][k4]);
    }

    float acc[2][4][4];
    #pragma unroll
    for (int mt = 0; mt < 2; mt++)
        #pragma unroll
        for (int nt = 0; nt < 4; nt++)
            #pragma unroll
            for (int i = 0; i < 4; i++) acc[mt][nt][i] = 0.f;

    int ntiles = K >> 4;
    cp_async16(dA0[0], Ap0); cp_async16(dA1[0], Ap1);
    cp_async16(dB0[0], Wp0);
    cp_commit();

    int buf = 0;
    for (int kt = 0; kt < ntiles; kt++) {
        bool more = (kt + 1 < ntiles);
        if (more) {
            int off = (kt + 1) * 16;
            cp_async16(dA0[buf ^ 1], Ap0 + off); cp_async16(dA1[buf ^ 1], Ap1 + off);
            cp_async16(dB0[buf ^ 1], Wp0 + off);
            cp_commit();
            cp_wait<1>();
        } else {
            cp_wait<0>();
        }
        __syncthreads();

        #pragma unroll
        for (int ks = 0; ks < 2; ks++) {
            int kc = ks * 8 + t;
            uint32_t af[2][4], bf[4][2];
            #pragma unroll
            for (int mt = 0; mt < 2; mt++) {
                int rr = wm * 32 + mt * 16 + q;
                af[mt][0] = __float_as_uint(As[buf][rr][kc]);
                af[mt][1] = __float_as_uint(As[buf][rr + 8][kc]);
                af[mt][2] = __float_as_uint(As[buf][rr][kc + 4]);
                af[mt][3] = __float_as_uint(As[buf][rr + 8][kc + 4]);
            }
            #pragma unroll
            for (int nt = 0; nt < 4; nt++) {
                int nn = wn * 32 + nt * 8 + q;
                bf[nt][0] = __float_as_uint(Bs[buf][nn][kc]);
                bf[nt][1] = __float_as_uint(Bs[buf][nn][kc + 4]);
            }
            #pragma unroll
            for (int mt = 0; mt < 2; mt++)
                #pragma unroll
                for (int nt = 0; nt < 4; nt++)
                    mma_tf32(acc[mt][nt], af[mt], bf[nt]);
        }
        __syncthreads();
        buf ^= 1;
    }

    #pragma unroll
    for (int mt = 0; mt < 2; mt++) {
        #pragma unroll
        for (int nt = 0; nt < 4; nt++) {
            int gm0 = m0 + wm * 32 + mt * 16 + q;
            int gn  = n0 + wn * 32 + nt * 8 + 2 * t;
            float bb0 = bias ? bias[gn]     : 0.f;
            float bb1 = bias ? bias[gn + 1] : 0.f;
            #pragma unroll
            for (int half = 0; half < 2; half++) {
                int gm = gm0 + half * 8;
                float c0 = acc[mt][nt][half * 2 + 0] + bb0;
                float c1 = acc[mt][nt][half * 2 + 1] + bb1;
                if (act == 1) { c0 = gelu_exact(c0); c1 = gelu_exact(c1); }
                size_t idx = (size_t)gm * N + gn;
                if (res) { c0 += res[idx]; c1 += res[idx + 1]; }
                *(float2*)(C + idx) = make_float2(c0, c1);
            }
        }
    }
}

static inline void gemm128(const float* A, const float* W, const float* bias,
                           const float* res, float* C, int M, int N, int K, int act) {
    dim3 grid(N / 64, M / 128);
    gemm128_kernel<<<grid, 256>>>(A, W, bias, res, C, M, N, K, act);
}

// ---------------------------------------------------------------------------
// 3xTF32 GEMM for slot-loop GEMMs, software-pipelined.
// ---------------------------------------------------------------------------
__global__ __launch_bounds__(256)
void gemm_tf32x3_kernel(const float* __restrict__ A, const float* __restrict__ W,
                        const float* __restrict__ bias, const float* __restrict__ res,
                        float* __restrict__ C, int M, int N, int K, int act) {
    __shared__ uint32_t Ah[64][20], Al[64][20], Bh[64][20], Bl[64][20];

    int tid = threadIdx.x;
    int m0 = blockIdx.y * 64, n0 = blockIdx.x * 64;
    int warp = tid >> 5, lane = tid & 31;
    int wm = warp & 1, wn = warp >> 1;
    int q = lane >> 2, t = lane & 3;

    int aRow = tid >> 2;
    int k4   = (tid & 3) << 2;
    const float* Aptr = A + (size_t)(m0 + aRow) * K + k4;
    const float* Wptr = W + (size_t)(n0 + aRow) * K + k4;

    float acc[2][2][4];
    #pragma unroll
    for (int mt = 0; mt < 2; mt++)
        #pragma unroll
        for (int nt = 0; nt < 2; nt++)
            #pragma unroll
            for (int i = 0; i < 4; i++) acc[mt][nt][i] = 0.f;

    int ntiles = K >> 4;
    float4 av = *(const float4*)Aptr;
    float4 bv = *(const float4*)Wptr;

    for (int kt = 0; kt < ntiles; kt++) {
        float a4[4] = {av.x, av.y, av.z, av.w};
        float b4[4] = {bv.x, bv.y, bv.z, bv.w};
        #pragma unroll
        for (int i = 0; i < 4; i++) {
            uint32_t h = f2tf32(a4[i]);
            Ah[aRow][k4 + i] = h;
            Al[aRow][k4 + i] = f2tf32(a4[i] - __uint_as_float(h));
            h = f2tf32(b4[i]);
            Bh[aRow][k4 + i] = h;
            Bl[aRow][k4 + i] = f2tf32(b4[i] - __uint_as_float(h));
        }
        __syncthreads();
        if (kt + 1 < ntiles) {
            av = *(const float4*)(Aptr + (kt + 1) * 16);
            bv = *(const float4*)(Wptr + (kt + 1) * 16);
        }
        #pragma unroll
        for (int ks = 0; ks < 2; ks++) {
            int kc = ks * 8 + t;
            uint32_t ah[2][4], al[2][4], bh[2][2], bl[2][2];
            #pragma unroll
            for (int mt = 0; mt < 2; mt++) {
                int rr = wm * 32 + mt * 16 + q;
                ah[mt][0] = Ah[rr][kc];   ah[mt][1] = Ah[rr + 8][kc];
                ah[mt][2] = Ah[rr][kc+4]; ah[mt][3] = Ah[rr + 8][kc+4];
                al[mt][0] = Al[rr][kc];   al[mt][1] = Al[rr + 8][kc];
                al[mt][2] = Al[rr][kc+4]; al[mt][3] = Al[rr + 8][kc+4];
            }
            #pragma unroll
            for (int nt = 0; nt < 2; nt++) {
                int nn = wn * 16 + nt * 8 + q;
                bh[nt][0] = Bh[nn][kc]; bh[nt][1] = Bh[nn][kc + 4];
                bl[nt][0] = Bl[nn][kc]; bl[nt][1] = Bl[nn][kc + 4];
            }
            #pragma unroll
            for (int mt = 0; mt < 2; mt++)
                #pragma unroll
                for (int nt = 0; nt < 2; nt++) {
                    mma_tf32(acc[mt][nt], al[mt], bh[nt]);
                    mma_tf32(acc[mt][nt], ah[mt], bl[nt]);
                    mma_tf32(acc[mt][nt], ah[mt], bh[nt]);
                }
        }
        __syncthreads();
    }

    #pragma unroll
    for (int mt = 0; mt < 2; mt++) {
        #pragma unroll
        for (int nt = 0; nt < 2; nt++) {
            int gm0 = m0 + wm * 32 + mt * 16 + q;
            int gn  = n0 + wn * 16 + nt * 8 + 2 * t;
            float b0 = bias ? bias[gn]     : 0.f;
            float b1 = bias ? bias[gn + 1] : 0.f;
            #pragma unroll
            for (int half = 0; half < 2; half++) {
                int gm = gm0 + half * 8;
                float c0 = acc[mt][nt][half * 2 + 0] + b0;
                float c1 = acc[mt][nt][half * 2 + 1] + b1;
                if (act == 1) { c0 = gelu_exact(c0); c1 = gelu_exact(c1); }
                size_t idx = (size_t)gm * N + gn;
                if (res) { c0 += res[idx]; c1 += res[idx + 1]; }
                *(float2*)(C + idx) = make_float2(c0, c1);
            }
        }
    }
}

static inline void gemm_x3(const float* A, const float* W, const float* bias,
                           const float* res, float* C, int M, int N, int K, int act) {
    dim3 grid(N / 64, M / 64);
    gemm_tf32x3_kernel<<<grid, 256>>>(A, W, bias, res, C, M, N, K, act);
}

// ---------------------------------------------------------------------------
// LayerNorm: warp per row, single pass, float4.
// ---------------------------------------------------------------------------
__global__ __launch_bounds__(256)
void ln_warp_kernel(const float* __restrict__ x, const float* __restrict__ g,
                    const float* __restrict__ b, float* __restrict__ y, int cols) {
    int row = blockIdx.x * 8 + (threadIdx.x >> 5);
    int lane = threadIdx.x & 31;
    int cols4 = cols >> 2;
    const float4* xr = (const float4*)(x + (size_t)row * cols);
    float s = 0.f, sq = 0.f;
    for (int c = lane; c < cols4; c += 32) {
        float4 v = xr[c];
        s  += (v.x + v.y) + (v.z + v.w);
        sq += v.x * v.x + v.y * v.y + v.z * v.z + v.w * v.w;
    }
    #pragma unroll
    for (int o = 16; o; o >>= 1) {
        s  += __shfl_xor_sync(0xffffffffu, s, o);
        sq += __shfl_xor_sync(0xffffffffu, sq, o);
    }
    float mean = s / (float)cols;
    float var = sq / (float)cols - mean * mean;
    float inv = rsqrtf(fmaxf(var, 0.f) + 1e-5f);
    float4* yr = (float4*)(y + (size_t)row * cols);
    const float4* g4 = (const float4*)g;
    const float4* b4 = (const float4*)b;
    for (int c = lane; c < cols4; c += 32) {
        float4 v = xr[c], gg = g4[c], bb = b4[c], o;
        o.x = (v.x - mean) * inv * gg.x + bb.x;
        o.y = (v.y - mean) * inv * gg.y + bb.y;
        o.z = (v.z - mean) * inv * gg.z + bb.z;
        o.w = (v.w - mean) * inv * gg.w + bb.w;
        yr[c] = o;
    }
}

// ---------------------------------------------------------------------------
// Attention via tf32 MMA, flash-style, RoPE fused (proven R10).
// Ps aliases Qs. Dynamic smem: 3 x 64 x 68 words = 52224 bytes.
// ---------------------------------------------------------------------------
__global__ __launch_bounds__(128)
void attn_mma_kernel(const float* __restrict__ qkv, float* __restrict__ ao) {
    extern __shared__ uint32_t sm[];
    uint32_t (*Qs)[68] = (uint32_t(*)[68])(sm);
    uint32_t (*Ks)[68] = (uint32_t(*)[68])(sm + 64 * 68);
    uint32_t (*Vs)[68] = (uint32_t(*)[68])(sm + 2 * 64 * 68);
    uint32_t (*Ps)[68] = Qs;                 // alias: Q consumed before P written

    int qt = blockIdx.x, h = blockIdx.y, b = blockIdx.z;
    int tid = threadIdx.x;
    int warp = tid >> 5, lane = tid & 31;
    int q = lane >> 2, t = lane & 3;

    const float* base = qkv + (size_t)b * 256 * 768 + h * 64;

    for (int idx = tid; idx < 64 * 16; idx += 128) {
        int r = idx >> 4, c4 = idx & 15;
        int n = qt * 64 + r;
        const float* rp = base + (size_t)n * 768;
        float4 v  = *(const float4*)(rp + c4 * 4);
        float4 cs = *(const float4*)(g_cosT + n * 64 + c4 * 4);
        float4 sn = *(const float4*)(g_sinT + n * 64 + c4 * 4);
        float rot0, rot1, rot2, rot3;
        if (c4 < 8) {
            float4 r0 = *(const float4*)(rp + 8 * c4);
            float4 r1 = *(const float4*)(rp + 8 * c4 + 4);
            rot0 = -r0.y; rot1 = -r0.w; rot2 = -r1.y; rot3 = -r1.w;
        } else {
            float4 r0 = *(const float4*)(rp + 8 * c4 - 64);
            float4 r1 = *(const float4*)(rp + 8 * c4 - 60);
            rot0 = r0.x; rot1 = r0.z; rot2 = r1.x; rot3 = r1.z;
        }
        Qs[r][c4 * 4 + 0] = f2tf32(v.x * cs.x + rot0 * sn.x);
        Qs[r][c4 * 4 + 1] = f2tf32(v.y * cs.y + rot1 * sn.y);
        Qs[r][c4 * 4 + 2] = f2tf32(v.z * cs.z + rot2 * sn.z);
        Qs[r][c4 * 4 + 3] = f2tf32(v.w * cs.w + rot3 * sn.w);
    }
    __syncthreads();

    uint32_t aq[8][4];
    #pragma unroll
    for (int kk = 0; kk < 8; kk++) {
        int rr = warp * 16 + q;
        aq[kk][0] = Qs[rr][8 * kk + t];
        aq[kk][1] = Qs[rr + 8][8 * kk + t];
        aq[kk][2] = Qs[rr][8 * kk + t + 4];
        aq[kk][3] = Qs[rr + 8][8 * kk + t + 4];
    }
    __syncthreads();

    float m0 = -1e30f, m1 = -1e30f, l0 = 0.f, l1 = 0.f;
    float o[8][4];
    #pragma unroll
    for (int nt = 0; nt < 8; nt++)
        #pragma unroll
        for (int i = 0; i < 4; i++) o[nt][i] = 0.f;

    for (int kt = 0; kt < 4; kt++) {
        for (int idx = tid; idx < 64 * 16; idx += 128) {
            int r = idx >> 4, c4 = idx & 15;
            int n = kt * 64 + r;
            const float* rp = base + (size_t)n * 768;
            const float* kp = rp + 256;
            float4 kv = *(const float4*)(kp + c4 * 4);
            float4 vv = *(const float4*)(rp + 512 + c4 * 4);
            float4 cs = *(const float4*)(g_cosT + n * 64 + c4 * 4);
            float4 sn = *(const float4*)(g_sinT + n * 64 + c4 * 4);
            float rot0, rot1, rot2, rot3;
            if (c4 < 8) {
                float4 r0 = *(const float4*)(kp + 8 * c4);
                float4 r1 = *(const float4*)(kp + 8 * c4 + 4);
                rot0 = -r0.y; rot1 = -r0.w; rot2 = -r1.y; rot3 = -r1.w;
            } else {
                float4 r0 = *(const float4*)(kp + 8 * c4 - 64);
                float4 r1 = *(const float4*)(kp + 8 * c4 - 60);
                rot0 = r0.x; rot1 = r0.z; rot2 = r1.x; rot3 = r1.z;
            }
            Ks[r][c4 * 4 + 0] = f2tf32(kv.x * cs.x + rot0 * sn.x);
            Ks[r][c4 * 4 + 1] = f2tf32(kv.y * cs.y + rot1 * sn.y);
            Ks[r][c4 * 4 + 2] = f2tf32(kv.z * cs.z + rot2 * sn.z);
            Ks[r][c4 * 4 + 3] = f2tf32(kv.w * cs.w + rot3 * sn.w);
            Vs[r][c4 * 4 + 0] = f2tf32(vv.x); Vs[r][c4 * 4 + 1] = f2tf32(vv.y);
            Vs[r][c4 * 4 + 2] = f2tf32(vv.z); Vs[r][c4 * 4 + 3] = f2tf32(vv.w);
        }
        __syncthreads();

        float s[8][4];
        #pragma unroll
        for (int nt = 0; nt < 8; nt++)
            #pragma unroll
            for (int i = 0; i < 4; i++) s[nt][i] = 0.f;
        #pragma unroll
        for (int kk = 0; kk < 8; kk++) {
            #pragma unroll
            for (int nt = 0; nt < 8; nt++) {
                uint32_t bf[2] = {Ks[nt * 8 + q][8 * kk + t],
                                  Ks[nt * 8 + q][8 * kk + t + 4]};
                mma_tf32(s[nt], aq[kk], bf);
            }
        }

        float rmax0 = -1e30f, rmax1 = -1e30f;
        #pragma unroll
        for (int nt = 0; nt < 8; nt++) {
            s[nt][0] *= 0.125f; s[nt][1] *= 0.125f;
            s[nt][2] *= 0.125f; s[nt][3] *= 0.125f;
            rmax0 = fmaxf(rmax0, fmaxf(s[nt][0], s[nt][1]));
            rmax1 = fmaxf(rmax1, fmaxf(s[nt][2], s[nt][3]));
        }
        rmax0 = fmaxf(rmax0, __shfl_xor_sync(0xffffffffu, rmax0, 1));
        rmax0 = fmaxf(rmax0, __shfl_xor_sync(0xffffffffu, rmax0, 2));
        rmax1 = fmaxf(rmax1, __shfl_xor_sync(0xffffffffu, rmax1, 1));
        rmax1 = fmaxf(rmax1, __shfl_xor_sync(0xffffffffu, rmax1, 2));
        float nm0 = fmaxf(m0, rmax0), nm1 = fmaxf(m1, rmax1);
        float c0 = __expf(m0 - nm0), c1 = __expf(m1 - nm1);
        m0 = nm0; m1 = nm1;
        float rs0 = 0.f, rs1 = 0.f;
        #pragma unroll
        for (int nt = 0; nt < 8; nt++) {
            s[nt][0] = __expf(s[nt][0] - m0);
            s[nt][1] = __expf(s[nt][1] - m0);
            s[nt][2] = __expf(s[nt][2] - m1);
            s[nt][3] = __expf(s[nt][3] - m1);
            rs0 += s[nt][0] + s[nt][1];
            rs1 += s[nt][2] + s[nt][3];
        }
        rs0 += __shfl_xor_sync(0xffffffffu, rs0, 1);
        rs0 += __shfl_xor_sync(0xffffffffu, rs0, 2);
        rs1 += __shfl_xor_sync(0xffffffffu, rs1, 1);
        rs1 += __shfl_xor_sync(0xffffffffu, rs1, 2);
        l0 = l0 * c0 + rs0;
        l1 = l1 * c1 + rs1;
        #pragma unroll
        for (int nt = 0; nt < 8; nt++) {
            o[nt][0] *= c0; o[nt][1] *= c0;
            o[nt][2] *= c1; o[nt][3] *= c1;
        }

        #pragma unroll
        for (int nt = 0; nt < 8; nt++) {
            int col = nt * 8 + 2 * t;
            Ps[warp * 16 + q][col]         = f2tf32(s[nt][0]);
            Ps[warp * 16 + q][col + 1]     = f2tf32(s[nt][1]);
            Ps[warp * 16 + q + 8][col]     = f2tf32(s[nt][2]);
            Ps[warp * 16 + q + 8][col + 1] = f2tf32(s[nt][3]);
        }
        __syncwarp();

        #pragma unroll
        for (int kk = 0; kk < 8; kk++) {
            uint32_t pa[4];
            pa[0] = Ps[warp * 16 + q][8 * kk + t];
            pa[1] = Ps[warp * 16 + q + 8][8 * kk + t];
            pa[2] = Ps[warp * 16 + q][8 * kk + t + 4];
            pa[3] = Ps[warp * 16 + q + 8][8 * kk + t + 4];
            #pragma unroll
            for (int nt = 0; nt < 8; nt++) {
                uint32_t bf[2] = {Vs[8 * kk + t][8 * nt + q],
                                  Vs[8 * kk + t + 4][8 * nt + q]};
                mma_tf32(o[nt], pa, bf);
            }
        }
        __syncthreads();
    }

    float inv0 = 1.f / l0, inv1 = 1.f / l1;
    int r0 = qt * 64 + warp * 16 + q;
    #pragma unroll
    for (int nt = 0; nt < 8; nt++) {
        int col = h * 64 + nt * 8 + 2 * t;
        float* p0 = ao + ((size_t)b * 256 + r0) * 256 + col;
        float* p1 = ao + ((size_t)b * 256 + r0 + 8) * 256 + col;
        *(float2*)p0 = make_float2(o[nt][0] * inv0, o[nt][1] * inv0);
        *(float2*)p1 = make_float2(o[nt][2] * inv1, o[nt][3] * inv1);
    }
}

// ---------------------------------------------------------------------------
// Collapsed slot path.
// ---------------------------------------------------------------------------
__global__ __launch_bounds__(256)
void colmean_kernel(const float* __restrict__ lnb, float* __restrict__ xbar) {
    int b = blockIdx.x;
    int c = threadIdx.x;
    const float* p = lnb + (size_t)b * 256 * 256 + c;
    float s = 0.f;
    #pragma unroll 8
    for (int n = 0; n < 256; n++) s += p[(size_t)n * 256];
    xbar[b * 256 + c] = s * (1.f / 256.f);
}

__global__ __launch_bounds__(256)
void gru_ln_kernel(const float* __restrict__ gi, const float* __restrict__ gh,
                   const float* __restrict__ bhh,
                   float* __restrict__ slots,
                   const float* __restrict__ nm_g, const float* __restrict__ nm_b,
                   float* __restrict__ sln, int first) {
    int row = blockIdx.x * 8 + (threadIdx.x >> 5);
    int lane = threadIdx.x & 31;
    const float* gir = gi + (size_t)row * 960;
    const float* ghr = first ? bhh : gh + (size_t)row * 960;
    float* sr = slots + (size_t)row * 320;
    float news[10];
    float s = 0.f, sq = 0.f;
    #pragma unroll
    for (int i = 0; i < 10; i++) {
        int f = lane + 32 * i;
        float ir = gir[f], iz = gir[320 + f], in_ = gir[640 + f];
        float hr = ghr[f], hz = ghr[320 + f], hn  = ghr[640 + f];
        float r = 1.f / (1.f + __expf(-(ir + hr)));
        float z = 1.f / (1.f + __expf(-(iz + hz)));
        float nn = tanhf(in_ + r * hn);
        float hprev = first ? 0.f : sr[f];
        float v = (1.f - z) * nn + z * hprev;
        news[i] = v;
        s += v; sq += v * v;
    }
    #pragma unroll
    for (int o = 16; o; o >>= 1) {
        s  += __shfl_xor_sync(0xffffffffu, s, o);
        sq += __shfl_xor_sync(0xffffffffu, sq, o);
    }
    float mean = s / 320.f;
    float var = sq / 320.f - mean * mean;
    float inv = rsqrtf(fmaxf(var, 0.f) + 1e-5f);
    float* lr = sln + (size_t)row * 320;
    #pragma unroll
    for (int i = 0; i < 10; i++) {
        int f = lane + 32 * i;
        sr[f] = news[i];
        lr[f] = (news[i] - mean) * inv * nm_g[f] + nm_b[f];
    }
}

__global__ void output_kernel(const float* __restrict__ slots,
                              float* __restrict__ out) {
    int idx = blockIdx.x * blockDim.x + threadIdx.x;
    const int SLOTS = Bc * NSc * FDc;      // 163840
    const int MASKS = Bc * NSc * Nc;       // 131072
    if (idx < SLOTS) {
        int b = idx / (NSc * FDc);
        int f = idx % FDc;
        out[idx] = slots[b * FDc + f];
    } else if (idx < SLOTS + MASKS) {
        out[idx] = 0.125f;
    }
}

// ---------------------------------------------------------------------------
// Host launcher
// ---------------------------------------------------------------------------
template <typename T>
static float* sym_addr(T& sym) {
    void* p = nullptr;
    cudaGetSymbolAddress(&p, sym);
    return (float*)p;
}

extern "C" void kernel_launch(void* const* d_in, const int* in_sizes, int n_in,
                              void* d_out, int out_size) {
    const float* state    = (const float*)d_in[0];
    const float* conv_w   = (const float*)d_in[1];
    const float* conv_b   = (const float*)d_in[2];
    const float* mlp_ln_g = (const float*)d_in[3];
    const float* mlp_ln_b = (const float*)d_in[4];
    const float* mlp_w1   = (const float*)d_in[5];
    const float* mlp_b1   = (const float*)d_in[6];
    const float* mlp_w2   = (const float*)d_in[7];
    const float* mlp_b2   = (const float*)d_in[8];
    const float* qkv_w    = (const float*)d_in[9];
    const float* qkv_b    = (const float*)d_in[10];
    const float* proj_w   = (const float*)d_in[11];
    const float* proj_b   = (const float*)d_in[12];
    const float* ni_g     = (const float*)d_in[13];
    const float* ni_b     = (const float*)d_in[14];
    const float* nm_g     = (const float*)d_in[17];
    const float* nm_b     = (const float*)d_in[18];
    const float* v_w      = (const float*)d_in[21];
    const float* gru_wih  = (const float*)d_in[22];
    const float* gru_whh  = (const float*)d_in[23];
    const float* gru_bih  = (const float*)d_in[24];
    const float* gru_bhh  = (const float*)d_in[25];
    const float* smlp_w1  = (const float*)d_in[26];
    const float* smlp_b1  = (const float*)d_in[27];
    const float* smlp_w2  = (const float*)d_in[28];
    const float* smlp_b2  = (const float*)d_in[29];
    float* out = (float*)d_out;

    float* P     = sym_addr(g_P);
    float* x0    = sym_addr(g_x0);
    float* lnb   = sym_addr(g_ln);
    float* h1    = sym_addr(g_h1);
    float* x2    = sym_addr(g_x2);
    float* ao    = sym_addr(g_ao);
    float* x3    = sym_addr(g_x3);
    float* xbar  = sym_addr(g_xbar);
    float* vbar  = sym_addr(g_vbar);
    float* slots = sym_addr(g_slots);
    float* sln   = sym_addr(g_sln);
    float* gi    = sym_addr(g_gi);
    float* gh    = sym_addr(g_gh);
    float* m1    = sym_addr(g_m1);

    const int ATTN_SMEM = 3 * 64 * 68 * 4;   // 52224 bytes
    cudaFuncSetAttribute(attn_mma_kernel,
                         cudaFuncAttributeMaxDynamicSharedMemorySize, ATTN_SMEM);

    // 1. RoPE tables + patch matrix
    rope_init_kernel<<<Nc, HDc>>>();
    patch_kernel<<<TOK / 4, 256>>>(state, P);

    // 2. Patch conv as GEMM
    gemm128(P, conv_w, conv_b, nullptr, x0, TOK, 256, 768, 0);

    // 3. Token MLP
    ln_warp_kernel<<<TOK / 8, 256>>>(x0, mlp_ln_g, mlp_ln_b, lnb, 256);
    gemm128(lnb, mlp_w1, mlp_b1, nullptr, h1, TOK, 512, 256, 1);
    gemm128(h1, mlp_w2, mlp_b2, nullptr, x2, TOK, 256, 512, 0);

    // 4. QKV + attention (RoPE fused) + proj (residual with x2)
    gemm128(x2, qkv_w, qkv_b, nullptr, P, TOK, 768, 256, 0);
    attn_mma_kernel<<<dim3(4, HEADSc, Bc), 128, ATTN_SMEM>>>(P, ao);
    gemm128(ao, proj_w, proj_b, x2, x3, TOK, 256, 256, 0);

    // 5. Norm + collapsed slot-attention prologue
    ln_warp_kernel<<<TOK / 8, 256>>>(x3, ni_g, ni_b, lnb, 256);
    colmean_kernel<<<Bc, 256>>>(lnb, xbar);
    gemm_x3(xbar, v_w, nullptr, nullptr, vbar, Bc, 320, 256, 0);
    gemm_x3(vbar, gru_wih, gru_bih, nullptr, gi, Bc, 960, 320, 0);

    // 6. Slot iterations (collapsed; it0 skips the gh GEMM — gh == bhh exactly)
    for (int it = 0; it < ITc; it++) {
        if (it == 0) {
            gru_ln_kernel<<<Bc / 8, 256>>>(gi, nullptr, gru_bhh, slots,
                                           nm_g, nm_b, sln, 1);
        } else {
            gemm_x3(slots, gru_whh, gru_bhh, nullptr, gh, Bc, 960, 320, 0);
            gru_ln_kernel<<<Bc / 8, 256>>>(gi, gh, gru_bhh, slots,
                                           nm_g, nm_b, sln, 0);
        }
        gemm_x3(sln, smlp_w1, smlp_b1, nullptr, m1, Bc, 640, 320, 1);
        gemm_x3(m1, smlp_w2, smlp_b2, slots, slots, Bc, 320, 640, 0);
    }

    // 7. Pack outputs
    int total = Bc * NSc * FDc + Bc * NSc * Nc;
    output_kernel<<<(total + 255) / 256, 256>>>(slots, out);
}

// round 15
// speedup vs baseline: 1.4193x; 1.4193x over previous
#include <cuda_runtime.h>
#include <math.h>
#include <stdint.h>

// ---------------------------------------------------------------------------
// Problem constants
// ---------------------------------------------------------------------------
constexpr int Bc = 64, Hc = 128, Wc = 128, PSc = 8, Gc = 16, Ec = 256;
constexpr int NSc = 8, ITc = 3, Vc = 10, FDc = 320, HEADSc = 4, HDc = 64;
constexpr int Nc = Gc * Gc;          // 256 tokens per image
constexpr int TOK = Bc * Nc;         // 16384 rows

// ---------------------------------------------------------------------------
// Device scratch
// ---------------------------------------------------------------------------
__device__ float g_P   [TOK * 768];        // im2col patches; reused for QKV
__device__ float g_x0  [TOK * Ec];
__device__ float g_ln  [TOK * Ec];
__device__ float g_h1  [TOK * 512];
__device__ float g_x2  [TOK * Ec];
__device__ float g_ao  [TOK * Ec];
__device__ float g_x3  [TOK * Ec];
__device__ float g_cosT[Nc * HDc];
__device__ float g_sinT[Nc * HDc];
// slot path (collapsed: one row per batch, slots identical across s)
__device__ float g_xbar [Bc * Ec];
__device__ float g_vbar [Bc * FDc];
__device__ float g_slots[Bc * FDc];
__device__ float g_sln  [Bc * FDc];
__device__ float g_gi   [Bc * 3 * FDc];
__device__ float g_gh   [Bc * 3 * FDc];
__device__ float g_m1   [Bc * 2 * FDc];

// ---------------------------------------------------------------------------
// Helpers
// ---------------------------------------------------------------------------
__device__ __forceinline__ float gelu_exact(float x) {
    return 0.5f * x * (1.0f + erff(x * 0.70710678118654752f));
}

__device__ __forceinline__ uint32_t f2tf32(float x) {
    uint32_t r;
    asm("cvt.rna.tf32.f32 %0, %1;" : "=r"(r) : "f"(x));
    return r;
}

__device__ __forceinline__ void mma_tf32(float (&d)[4], const uint32_t (&a)[4],
                                         const uint32_t (&b)[2]) {
    asm volatile(
        "mma.sync.aligned.m16n8k8.row.col.f32.tf32.tf32.f32 "
        "{%0,%1,%2,%3}, {%4,%5,%6,%7}, {%8,%9}, {%0,%1,%2,%3};\n"
        : "+f"(d[0]), "+f"(d[1]), "+f"(d[2]), "+f"(d[3])
        : "r"(a[0]), "r"(a[1]), "r"(a[2]), "r"(a[3]), "r"(b[0]), "r"(b[1]));
}

__device__ __forceinline__ uint32_t smem_u32(const void* p) {
    return (uint32_t)__cvta_generic_to_shared(p);
}

__device__ __forceinline__ void cp_async16(uint32_t dst, const void* src) {
    asm volatile("cp.async.ca.shared.global [%0], [%1], 16;\n"
                 :: "r"(dst), "l"(src));
}

__device__ __forceinline__ void cp_commit() {
    asm volatile("cp.async.commit_group;\n");
}

template <int N>
__device__ __forceinline__ void cp_wait() {
    asm volatile("cp.async.wait_group %0;\n" :: "n"(N));
}

// ---------------------------------------------------------------------------
// RoPE tables
// ---------------------------------------------------------------------------
__global__ void rope_init_kernel() {
    int n = blockIdx.x;          // 0..255
    int d = threadIdx.x;         // 0..63
    int gy = n >> 4, gx = n & 15;
    int pos = (d < 32) ? gy : gx;
    int dd  = (d < 32) ? d : d - 32;
    float val;
    if (dd < 16) {
        float inv = expf(-9.210340371976184f * (2.0f * dd) / 32.0f);
        val = sinf((float)pos * inv);
    } else {
        float inv = expf(-9.210340371976184f * (2.0f * (dd - 16)) / 32.0f);
        val = cosf((float)pos * inv);
    }
    g_cosT[n * 64 + d] = cosf(val);
    g_sinT[n * 64 + d] = sinf(val);
}

// ---------------------------------------------------------------------------
// Patch / im2col builder: 4 tokens per 256-thread block.
// ---------------------------------------------------------------------------
__global__ __launch_bounds__(256)
void patch_kernel(const float* __restrict__ state, float* __restrict__ P) {
    int bn = blockIdx.x * 4 + (threadIdx.x >> 6);
    int b = bn >> 8, n = bn & 255;
    int gy = n >> 4, gx = n & 15;
    int p = threadIdx.x & 63;          // 0..63
    int py = p >> 3, px = p & 7;
    int y = gy * 8 + py, x = gx * 8 + px;
    const float* sb = state + (size_t)b * Hc * Wc;
    float* row = P + (size_t)bn * 768;
    for (int k = p; k < 768; k += 64) row[k] = 0.f;

    float v[3][3];
    #pragma unroll
    for (int di = 0; di < 3; di++) {
        int yy = min(max(y + di - 1, 0), Hc - 1);
        #pragma unroll
        for (int dj = 0; dj < 3; dj++) {
            int xx = min(max(x + dj - 1, 0), Wc - 1);
            v[di][dj] = sb[yy * Wc + xx];
        }
    }
    float sx = (v[0][2] + 2.f * v[1][2] + v[2][2]) - (v[0][0] + 2.f * v[1][0] + v[2][0]);
    float sy = (v[2][0] + 2.f * v[2][1] + v[2][2]) - (v[0][0] + 2.f * v[0][1] + v[0][2]);
    int id = (int)sb[y * Wc + x];
    __syncthreads();
    row[id * 64 + p]  = 1.f;
    row[640 + p]      = sx;
    row[704 + p]      = sy;
}

// ---------------------------------------------------------------------------
// TF32 tensor-core GEMM with cp.async double-buffered mainloop (proven R9/R12).
// BM=128, BN=128, BK=16, 256 threads (8 warps), warp tile m32 x n64.
// ---------------------------------------------------------------------------
__global__ __launch_bounds__(256, 2)
void gemm128_kernel(const float* __restrict__ A,
                    const float* __restrict__ W,
                    const float* __restrict__ bias, const float* __restrict__ res,
                    float* __restrict__ C,
                    int M, int N, int K, int act) {
    __shared__ float As[2][128][20];
    __shared__ float Bs[2][128][20];

    int tid = threadIdx.x;
    int m0 = blockIdx.y * 128, n0 = blockIdx.x * 128;
    int warp = tid >> 5, lane = tid & 31;
    int wm = warp & 3, wn = warp >> 2;
    int q = lane >> 2, t = lane & 3;

    int r  = tid >> 2;
    int k4 = (tid & 3) << 2;

    const float* Ap0 = A + (size_t)(m0 + r) * K + k4;
    const float* Ap1 = Ap0 + (size_t)64 * K;
    const float* Wp0 = W + (size_t)(n0 + r) * K + k4;
    const float* Wp1 = W + (size_t)(n0 + r + 64) * K + k4;

    uint32_t dA0[2], dA1[2], dB0[2], dB1[2];
    #pragma unroll
    for (int s = 0; s < 2; s++) {
        dA0[s] = smem_u32(&As[s][r][k4]);
        dA1[s] = smem_u32(&As[s][r + 64][k4]);
        dB0[s] = smem_u32(&Bs[s][r][k4]);
        dB1[s] = smem_u32(&Bs[s][r + 64][k4]);
    }

    float acc[2][8][4];
    #pragma unroll
    for (int mt = 0; mt < 2; mt++)
        #pragma unroll
        for (int nt = 0; nt < 8; nt++)
            #pragma unroll
            for (int i = 0; i < 4; i++) acc[mt][nt][i] = 0.f;

    int ntiles = K >> 4;
    cp_async16(dA0[0], Ap0); cp_async16(dA1[0], Ap1);
    cp_async16(dB0[0], Wp0); cp_async16(dB1[0], Wp1);
    cp_commit();

    int buf = 0;
    for (int kt = 0; kt < ntiles; kt++) {
        bool more = (kt + 1 < ntiles);
        if (more) {
            int off = (kt + 1) * 16;
            cp_async16(dA0[buf ^ 1], Ap0 + off); cp_async16(dA1[buf ^ 1], Ap1 + off);
            cp_async16(dB0[buf ^ 1], Wp0 + off); cp_async16(dB1[buf ^ 1], Wp1 + off);
            cp_commit();
            cp_wait<1>();
        } else {
            cp_wait<0>();
        }
        __syncthreads();

        #pragma unroll
        for (int ks = 0; ks < 2; ks++) {
            int kc = ks * 8 + t;
            uint32_t af[2][4], bf[8][2];
            #pragma unroll
            for (int mt = 0; mt < 2; mt++) {
                int rr = wm * 32 + mt * 16 + q;
                af[mt][0] = __float_as_uint(As[buf][rr][kc]);
                af[mt][1] = __float_as_uint(As[buf][rr + 8][kc]);
                af[mt][2] = __float_as_uint(As[buf][rr][kc + 4]);
                af[mt][3] = __float_as_uint(As[buf][rr + 8][kc + 4]);
            }
            #pragma unroll
            for (int nt = 0; nt < 8; nt++) {
                int nn = wn * 64 + nt * 8 + q;
                bf[nt][0] = __float_as_uint(Bs[buf][nn][kc]);
                bf[nt][1] = __float_as_uint(Bs[buf][nn][kc + 4]);
            }
            #pragma unroll
            for (int mt = 0; mt < 2; mt++)
                #pragma unroll
                for (int nt = 0; nt < 8; nt++)
                    mma_tf32(acc[mt][nt], af[mt], bf[nt]);
        }
        __syncthreads();
        buf ^= 1;
    }

    #pragma unroll
    for (int mt = 0; mt < 2; mt++) {
        #pragma unroll
        for (int nt = 0; nt < 8; nt++) {
            int gm0 = m0 + wm * 32 + mt * 16 + q;
            int gn  = n0 + wn * 64 + nt * 8 + 2 * t;
            float bb0 = bias ? bias[gn]     : 0.f;
            float bb1 = bias ? bias[gn + 1] : 0.f;
            #pragma unroll
            for (int half = 0; half < 2; half++) {
                int gm = gm0 + half * 8;
                float c0 = acc[mt][nt][half * 2 + 0] + bb0;
                float c1 = acc[mt][nt][half * 2 + 1] + bb1;
                if (act == 1) { c0 = gelu_exact(c0); c1 = gelu_exact(c1); }
                size_t idx = (size_t)gm * N + gn;
                if (res) { c0 += res[idx]; c1 += res[idx + 1]; }
                *(float2*)(C + idx) = make_float2(c0, c1);
            }
        }
    }
}

static inline void gemm128(const float* A, const float* W, const float* bias,
                           const float* res, float* C, int M, int N, int K, int act) {
    dim3 grid(N / 128, M / 128);
    gemm128_kernel<<<grid, 256>>>(A, W, bias, res, C, M, N, K, act);
}

// ---------------------------------------------------------------------------
// Slot matvec: C[64, N] = act(A[64,K] @ W[N,K]^T + bias) (+res).
// grid (N/8, 8): block handles 8 m-rows x 8 j-cols; warp w -> column j.
// A tile staged in smem; plain fp32 FMA + shfl reduce. Massively parallel,
// no serial multi-tile loop (R6 lesson: per-stage grids, not in-block chains).
// ---------------------------------------------------------------------------
__global__ __launch_bounds__(256)
void slot_mv_kernel(const float* __restrict__ A, const float* __restrict__ W,
                    const float* __restrict__ bias, const float* __restrict__ res,
                    float* __restrict__ C, int N, int K, int act) {
    extern __shared__ float Asm[];     // [8][K]
    int jt = blockIdx.x, mt = blockIdx.y;
    int tid = threadIdx.x, warp = tid >> 5, lane = tid & 31;

    for (int i = tid; i < 8 * K; i += 256)
        Asm[i] = A[(size_t)(mt * 8 + i / K) * K + (i % K)];
    __syncthreads();

    int j = jt * 8 + warp;
    const float* wr = W + (size_t)j * K;
    float acc[8] = {};
    for (int k = lane; k < K; k += 32) {
        float wv = wr[k];
        #pragma unroll
        for (int m = 0; m < 8; m++) acc[m] += wv * Asm[m * K + k];
    }
    #pragma unroll
    for (int m = 0; m < 8; m++)
        #pragma unroll
        for (int o = 16; o; o >>= 1)
            acc[m] += __shfl_xor_sync(0xffffffffu, acc[m], o);

    if (lane == 0) {
        float b = bias ? bias[j] : 0.f;
        #pragma unroll
        for (int m = 0; m < 8; m++) {
            float c = acc[m] + b;
            if (act == 1) c = gelu_exact(c);
            size_t idx = (size_t)(mt * 8 + m) * N + j;
            if (res) c += res[idx];
            C[idx] = c;
        }
    }
}

static inline void slot_mv(const float* A, const float* W, const float* bias,
                           const float* res, float* C, int N, int K, int act) {
    dim3 grid(N / 8, 8);
    slot_mv_kernel<<<grid, 256, 8 * K * 4>>>(A, W, bias, res, C, N, K, act);
}

// ---------------------------------------------------------------------------
// LayerNorm: warp per row, single pass, float4.
// ---------------------------------------------------------------------------
__global__ __launch_bounds__(256)
void ln_warp_kernel(const float* __restrict__ x, const float* __restrict__ g,
                    const float* __restrict__ b, float* __restrict__ y, int cols) {
    int row = blockIdx.x * 8 + (threadIdx.x >> 5);
    int lane = threadIdx.x & 31;
    int cols4 = cols >> 2;
    const float4* xr = (const float4*)(x + (size_t)row * cols);
    float s = 0.f, sq = 0.f;
    for (int c = lane; c < cols4; c += 32) {
        float4 v = xr[c];
        s  += (v.x + v.y) + (v.z + v.w);
        sq += v.x * v.x + v.y * v.y + v.z * v.z + v.w * v.w;
    }
    #pragma unroll
    for (int o = 16; o; o >>= 1) {
        s  += __shfl_xor_sync(0xffffffffu, s, o);
        sq += __shfl_xor_sync(0xffffffffu, sq, o);
    }
    float mean = s / (float)cols;
    float var = sq / (float)cols - mean * mean;
    float inv = rsqrtf(fmaxf(var, 0.f) + 1e-5f);
    float4* yr = (float4*)(y + (size_t)row * cols);
    const float4* g4 = (const float4*)g;
    const float4* b4 = (const float4*)b;
    for (int c = lane; c < cols4; c += 32) {
        float4 v = xr[c], gg = g4[c], bb = b4[c], o;
        o.x = (v.x - mean) * inv * gg.x + bb.x;
        o.y = (v.y - mean) * inv * gg.y + bb.y;
        o.z = (v.z - mean) * inv * gg.z + bb.z;
        o.w = (v.w - mean) * inv * gg.w + bb.w;
        yr[c] = o;
    }
}

// ---------------------------------------------------------------------------
// Attention via tf32 MMA, flash-style, RoPE fused (proven R10).
// Ps aliases Qs. Dynamic smem: 3 x 64 x 68 words = 52224 bytes.
// ---------------------------------------------------------------------------
__global__ __launch_bounds__(128)
void attn_mma_kernel(const float* __restrict__ qkv, float* __restrict__ ao) {
    extern __shared__ uint32_t sm[];
    uint32_t (*Qs)[68] = (uint32_t(*)[68])(sm);
    uint32_t (*Ks)[68] = (uint32_t(*)[68])(sm + 64 * 68);
    uint32_t (*Vs)[68] = (uint32_t(*)[68])(sm + 2 * 64 * 68);
    uint32_t (*Ps)[68] = Qs;                 // alias: Q consumed before P written

    int qt = blockIdx.x, h = blockIdx.y, b = blockIdx.z;
    int tid = threadIdx.x;
    int warp = tid >> 5, lane = tid & 31;
    int q = lane >> 2, t = lane & 3;

    const float* base = qkv + (size_t)b * 256 * 768 + h * 64;

    for (int idx = tid; idx < 64 * 16; idx += 128) {
        int r = idx >> 4, c4 = idx & 15;
        int n = qt * 64 + r;
        const float* rp = base + (size_t)n * 768;
        float4 v  = *(const float4*)(rp + c4 * 4);
        float4 cs = *(const float4*)(g_cosT + n * 64 + c4 * 4);
        float4 sn = *(const float4*)(g_sinT + n * 64 + c4 * 4);
        float rot0, rot1, rot2, rot3;
        if (c4 < 8) {
            float4 r0 = *(const float4*)(rp + 8 * c4);
            float4 r1 = *(const float4*)(rp + 8 * c4 + 4);
            rot0 = -r0.y; rot1 = -r0.w; rot2 = -r1.y; rot3 = -r1.w;
        } else {
            float4 r0 = *(const float4*)(rp + 8 * c4 - 64);
            float4 r1 = *(const float4*)(rp + 8 * c4 - 60);
            rot0 = r0.x; rot1 = r0.z; rot2 = r1.x; rot3 = r1.z;
        }
        Qs[r][c4 * 4 + 0] = f2tf32(v.x * cs.x + rot0 * sn.x);
        Qs[r][c4 * 4 + 1] = f2tf32(v.y * cs.y + rot1 * sn.y);
        Qs[r][c4 * 4 + 2] = f2tf32(v.z * cs.z + rot2 * sn.z);
        Qs[r][c4 * 4 + 3] = f2tf32(v.w * cs.w + rot3 * sn.w);
    }
    __syncthreads();

    uint32_t aq[8][4];
    #pragma unroll
    for (int kk = 0; kk < 8; kk++) {
        int rr = warp * 16 + q;
        aq[kk][0] = Qs[rr][8 * kk + t];
        aq[kk][1] = Qs[rr + 8][8 * kk + t];
        aq[kk][2] = Qs[rr][8 * kk + t + 4];
        aq[kk][3] = Qs[rr + 8][8 * kk + t + 4];
    }
    __syncthreads();

    float m0 = -1e30f, m1 = -1e30f, l0 = 0.f, l1 = 0.f;
    float o[8][4];
    #pragma unroll
    for (int nt = 0; nt < 8; nt++)
        #pragma unroll
        for (int i = 0; i < 4; i++) o[nt][i] = 0.f;

    for (int kt = 0; kt < 4; kt++) {
        for (int idx = tid; idx < 64 * 16; idx += 128) {
            int r = idx >> 4, c4 = idx & 15;
            int n = kt * 64 + r;
            const float* rp = base + (size_t)n * 768;
            const float* kp = rp + 256;
            float4 kv = *(const float4*)(kp + c4 * 4);
            float4 vv = *(const float4*)(rp + 512 + c4 * 4);
            float4 cs = *(const float4*)(g_cosT + n * 64 + c4 * 4);
            float4 sn = *(const float4*)(g_sinT + n * 64 + c4 * 4);
            float rot0, rot1, rot2, rot3;
            if (c4 < 8) {
                float4 r0 = *(const float4*)(kp + 8 * c4);
                float4 r1 = *(const float4*)(kp + 8 * c4 + 4);
                rot0 = -r0.y; rot1 = -r0.w; rot2 = -r1.y; rot3 = -r1.w;
            } else {
                float4 r0 = *(const float4*)(kp + 8 * c4 - 64);
                float4 r1 = *(const float4*)(kp + 8 * c4 - 60);
                rot0 = r0.x; rot1 = r0.z; rot2 = r1.x; rot3 = r1.z;
            }
            Ks[r][c4 * 4 + 0] = f2tf32(kv.x * cs.x + rot0 * sn.x);
            Ks[r][c4 * 4 + 1] = f2tf32(kv.y * cs.y + rot1 * sn.y);
            Ks[r][c4 * 4 + 2] = f2tf32(kv.z * cs.z + rot2 * sn.z);
            Ks[r][c4 * 4 + 3] = f2tf32(kv.w * cs.w + rot3 * sn.w);
            Vs[r][c4 * 4 + 0] = f2tf32(vv.x); Vs[r][c4 * 4 + 1] = f2tf32(vv.y);
            Vs[r][c4 * 4 + 2] = f2tf32(vv.z); Vs[r][c4 * 4 + 3] = f2tf32(vv.w);
        }
        __syncthreads();

        float s[8][4];
        #pragma unroll
        for (int nt = 0; nt < 8; nt++)
            #pragma unroll
            for (int i = 0; i < 4; i++) s[nt][i] = 0.f;
        #pragma unroll
        for (int kk = 0; kk < 8; kk++) {
            #pragma unroll
            for (int nt = 0; nt < 8; nt++) {
                uint32_t bf[2] = {Ks[nt * 8 + q][8 * kk + t],
                                  Ks[nt * 8 + q][8 * kk + t + 4]};
                mma_tf32(s[nt], aq[kk], bf);
            }
        }

        float rmax0 = -1e30f, rmax1 = -1e30f;
        #pragma unroll
        for (int nt = 0; nt < 8; nt++) {
            s[nt][0] *= 0.125f; s[nt][1] *= 0.125f;
            s[nt][2] *= 0.125f; s[nt][3] *= 0.125f;
            rmax0 = fmaxf(rmax0, fmaxf(s[nt][0], s[nt][1]));
            rmax1 = fmaxf(rmax1, fmaxf(s[nt][2], s[nt][3]));
        }
        rmax0 = fmaxf(rmax0, __shfl_xor_sync(0xffffffffu, rmax0, 1));
        rmax0 = fmaxf(rmax0, __shfl_xor_sync(0xffffffffu, rmax0, 2));
        rmax1 = fmaxf(rmax1, __shfl_xor_sync(0xffffffffu, rmax1, 1));
        rmax1 = fmaxf(rmax1, __shfl_xor_sync(0xffffffffu, rmax1, 2));
        float nm0 = fmaxf(m0, rmax0), nm1 = fmaxf(m1, rmax1);
        float c0 = __expf(m0 - nm0), c1 = __expf(m1 - nm1);
        m0 = nm0; m1 = nm1;
        float rs0 = 0.f, rs1 = 0.f;
        #pragma unroll
        for (int nt = 0; nt < 8; nt++) {
            s[nt][0] = __expf(s[nt][0] - m0);
            s[nt][1] = __expf(s[nt][1] - m0);
            s[nt][2] = __expf(s[nt][2] - m1);
            s[nt][3] = __expf(s[nt][3] - m1);
            rs0 += s[nt][0] + s[nt][1];
            rs1 += s[nt][2] + s[nt][3];
        }
        rs0 += __shfl_xor_sync(0xffffffffu, rs0, 1);
        rs0 += __shfl_xor_sync(0xffffffffu, rs0, 2);
        rs1 += __shfl_xor_sync(0xffffffffu, rs1, 1);
        rs1 += __shfl_xor_sync(0xffffffffu, rs1, 2);
        l0 = l0 * c0 + rs0;
        l1 = l1 * c1 + rs1;
        #pragma unroll
        for (int nt = 0; nt < 8; nt++) {
            o[nt][0] *= c0; o[nt][1] *= c0;
            o[nt][2] *= c1; o[nt][3] *= c1;
        }

        #pragma unroll
        for (int nt = 0; nt < 8; nt++) {
            int col = nt * 8 + 2 * t;
            Ps[warp * 16 + q][col]         = f2tf32(s[nt][0]);
            Ps[warp * 16 + q][col + 1]     = f2tf32(s[nt][1]);
            Ps[warp * 16 + q + 8][col]     = f2tf32(s[nt][2]);
            Ps[warp * 16 + q + 8][col + 1] = f2tf32(s[nt][3]);
        }
        __syncwarp();

        #pragma unroll
        for (int kk = 0; kk < 8; kk++) {
            uint32_t pa[4];
            pa[0] = Ps[warp * 16 + q][8 * kk + t];
            pa[1] = Ps[warp * 16 + q + 8][8 * kk + t];
            pa[2] = Ps[warp * 16 + q][8 * kk + t + 4];
            pa[3] = Ps[warp * 16 + q + 8][8 * kk + t + 4];
            #pragma unroll
            for (int nt = 0; nt < 8; nt++) {
                uint32_t bf[2] = {Vs[8 * kk + t][8 * nt + q],
                                  Vs[8 * kk + t + 4][8 * nt + q]};
                mma_tf32(o[nt], pa, bf);
            }
        }
        __syncthreads();
    }

    float inv0 = 1.f / l0, inv1 = 1.f / l1;
    int r0 = qt * 64 + warp * 16 + q;
    #pragma unroll
    for (int nt = 0; nt < 8; nt++) {
        int col = h * 64 + nt * 8 + 2 * t;
        float* p0 = ao + ((size_t)b * 256 + r0) * 256 + col;
        float* p1 = ao + ((size_t)b * 256 + r0 + 8) * 256 + col;
        *(float2*)p0 = make_float2(o[nt][0] * inv0, o[nt][1] * inv0);
        *(float2*)p1 = make_float2(o[nt][2] * inv1, o[nt][3] * inv1);
    }
}

// ---------------------------------------------------------------------------
// Collapsed slot path.
// ---------------------------------------------------------------------------
__global__ __launch_bounds__(256)
void colmean_kernel(const float* __restrict__ lnb, float* __restrict__ xbar) {
    int b = blockIdx.x;
    int c = threadIdx.x;
    const float* p = lnb + (size_t)b * 256 * 256 + c;
    float s = 0.f;
    #pragma unroll 8
    for (int n = 0; n < 256; n++) s += p[(size_t)n * 256];
    xbar[b * 256 + c] = s * (1.f / 256.f);
}

__global__ __launch_bounds__(256)
void gru_ln_kernel(const float* __restrict__ gi, const float* __restrict__ gh,
                   const float* __restrict__ bhh,
                   float* __restrict__ slots,
                   const float* __restrict__ nm_g, const float* __restrict__ nm_b,
                   float* __restrict__ sln, int first) {
    int row = blockIdx.x * 8 + (threadIdx.x >> 5);
    int lane = threadIdx.x & 31;
    const float* gir = gi + (size_t)row * 960;
    const float* ghr = first ? bhh : gh + (size_t)row * 960;
    float* sr = slots + (size_t)row * 320;
    float news[10];
    float s = 0.f, sq = 0.f;
    #pragma unroll
    for (int i = 0; i < 10; i++) {
        int f = lane + 32 * i;
        float ir = gir[f], iz = gir[320 + f], in_ = gir[640 + f];
        float hr = ghr[f], hz = ghr[320 + f], hn  = ghr[640 + f];
        float r = 1.f / (1.f + __expf(-(ir + hr)));
        float z = 1.f / (1.f + __expf(-(iz + hz)));
        float nn = tanhf(in_ + r * hn);
        float hprev = first ? 0.f : sr[f];
        float v = (1.f - z) * nn + z * hprev;
        news[i] = v;
        s += v; sq += v * v;
    }
    #pragma unroll
    for (int o = 16; o; o >>= 1) {
        s  += __shfl_xor_sync(0xffffffffu, s, o);
        sq += __shfl_xor_sync(0xffffffffu, sq, o);
    }
    float mean = s / 320.f;
    float var = sq / 320.f - mean * mean;
    float inv = rsqrtf(fmaxf(var, 0.f) + 1e-5f);
    float* lr = sln + (size_t)row * 320;
    #pragma unroll
    for (int i = 0; i < 10; i++) {
        int f = lane + 32 * i;
        sr[f] = news[i];
        lr[f] = (news[i] - mean) * inv * nm_g[f] + nm_b[f];
    }
}

__global__ void output_kernel(const float* __restrict__ slots,
                              float* __restrict__ out) {
    int idx = blockIdx.x * blockDim.x + threadIdx.x;
    const int SLOTS = Bc * NSc * FDc;      // 163840
    const int MASKS = Bc * NSc * Nc;       // 131072
    if (idx < SLOTS) {
        int b = idx / (NSc * FDc);
        int f = idx % FDc;
        out[idx] = slots[b * FDc + f];
    } else if (idx < SLOTS + MASKS) {
        out[idx] = 0.125f;
    }
}

// ---------------------------------------------------------------------------
// Host launcher
// ---------------------------------------------------------------------------
template <typename T>
static float* sym_addr(T& sym) {
    void* p = nullptr;
    cudaGetSymbolAddress(&p, sym);
    return (float*)p;
}

extern "C" void kernel_launch(void* const* d_in, const int* in_sizes, int n_in,
                              void* d_out, int out_size) {
    const float* state    = (const float*)d_in[0];
    const float* conv_w   = (const float*)d_in[1];
    const float* conv_b   = (const float*)d_in[2];
    const float* mlp_ln_g = (const float*)d_in[3];
    const float* mlp_ln_b = (const float*)d_in[4];
    const float* mlp_w1   = (const float*)d_in[5];
    const float* mlp_b1   = (const float*)d_in[6];
    const float* mlp_w2   = (const float*)d_in[7];
    const float* mlp_b2   = (const float*)d_in[8];
    const float* qkv_w    = (const float*)d_in[9];
    const float* qkv_b    = (const float*)d_in[10];
    const float* proj_w   = (const float*)d_in[11];
    const float* proj_b   = (const float*)d_in[12];
    const float* ni_g     = (const float*)d_in[13];
    const float* ni_b     = (const float*)d_in[14];
    const float* nm_g     = (const float*)d_in[17];
    const float* nm_b     = (const float*)d_in[18];
    const float* v_w      = (const float*)d_in[21];
    const float* gru_wih  = (const float*)d_in[22];
    const float* gru_whh  = (const float*)d_in[23];
    const float* gru_bih  = (const float*)d_in[24];
    const float* gru_bhh  = (const float*)d_in[25];
    const float* smlp_w1  = (const float*)d_in[26];
    const float* smlp_b1  = (const float*)d_in[27];
    const float* smlp_w2  = (const float*)d_in[28];
    const float* smlp_b2  = (const float*)d_in[29];
    float* out = (float*)d_out;

    float* P     = sym_addr(g_P);
    float* x0    = sym_addr(g_x0);
    float* lnb   = sym_addr(g_ln);
    float* h1    = sym_addr(g_h1);
    float* x2    = sym_addr(g_x2);
    float* ao    = sym_addr(g_ao);
    float* x3    = sym_addr(g_x3);
    float* xbar  = sym_addr(g_xbar);
    float* vbar  = sym_addr(g_vbar);
    float* slots = sym_addr(g_slots);
    float* sln   = sym_addr(g_sln);
    float* gi    = sym_addr(g_gi);
    float* gh    = sym_addr(g_gh);
    float* m1    = sym_addr(g_m1);

    const int ATTN_SMEM = 3 * 64 * 68 * 4;   // 52224 bytes
    cudaFuncSetAttribute(attn_mma_kernel,
                         cudaFuncAttributeMaxDynamicSharedMemorySize, ATTN_SMEM);

    // 1. RoPE tables + patch matrix
    rope_init_kernel<<<Nc, HDc>>>();
    patch_kernel<<<TOK / 4, 256>>>(state, P);

    // 2. Patch conv as GEMM
    gemm128(P, conv_w, conv_b, nullptr, x0, TOK, 256, 768, 0);

    // 3. Token MLP
    ln_warp_kernel<<<TOK / 8, 256>>>(x0, mlp_ln_g, mlp_ln_b, lnb, 256);
    gemm128(lnb, mlp_w1, mlp_b1, nullptr, h1, TOK, 512, 256, 1);
    gemm128(h1, mlp_w2, mlp_b2, nullptr, x2, TOK, 256, 512, 0);

    // 4. QKV + attention (RoPE fused) + proj (residual with x2)
    gemm128(x2, qkv_w, qkv_b, nullptr, P, TOK, 768, 256, 0);
    attn_mma_kernel<<<dim3(4, HEADSc, Bc), 128, ATTN_SMEM>>>(P, ao);
    gemm128(ao, proj_w, proj_b, x2, x3, TOK, 256, 256, 0);

    // 5. Norm + collapsed slot-attention prologue (parallel fp32 matvecs)
    ln_warp_kernel<<<TOK / 8, 256>>>(x3, ni_g, ni_b, lnb, 256);
    colmean_kernel<<<Bc, 256>>>(lnb, xbar);
    slot_mv(xbar, v_w, nullptr, nullptr, vbar, 320, 256, 0);
    slot_mv(vbar, gru_wih, gru_bih, nullptr, gi, 960, 320, 0);

    // 6. Slot iterations (collapsed; it0 skips the gh matvec — gh == bhh exactly)
    for (int it = 0; it < ITc; it++) {
        if (it == 0) {
            gru_ln_kernel<<<Bc / 8, 256>>>(gi, nullptr, gru_bhh, slots,
                                           nm_g, nm_b, sln, 1);
        } else {
            slot_mv(slots, gru_whh, gru_bhh, nullptr, gh, 960, 320, 0);
            gru_ln_kernel<<<Bc / 8, 256>>>(gi, gh, gru_bhh, slots,
                                           nm_g, nm_b, sln, 0);
        }
        slot_mv(sln, smlp_w1, smlp_b1, nullptr, m1, 640, 320, 1);
        slot_mv(m1, smlp_w2, smlp_b2, slots, slots, 320, 640, 0);
    }

    // 7. Pack outputs
    int total = Bc * NSc * FDc + Bc * NSc * Nc;
    output_kernel<<<(total + 255) / 256, 256>>>(slots, out);
}

// round 17
// speedup vs baseline: 1.5479x; 1.0906x over previous
#include <cuda_runtime.h>
#include <cuda_fp16.h>
#include <math.h>
#include <stdint.h>

// ---------------------------------------------------------------------------
// Problem constants
// ---------------------------------------------------------------------------
constexpr int Bc = 64, Hc = 128, Wc = 128, PSc = 8, Gc = 16, Ec = 256;
constexpr int NSc = 8, ITc = 3, Vc = 10, FDc = 320, HEADSc = 4, HDc = 64;
constexpr int Nc = Gc * Gc;          // 256 tokens per image
constexpr int TOK = Bc * Nc;         // 16384 rows

// ---------------------------------------------------------------------------
// Device scratch
// ---------------------------------------------------------------------------
__device__ float g_P   [TOK * 768];        // im2col patches; reused for QKV
__device__ float g_x0  [TOK * Ec];
__device__ float g_ln  [TOK * Ec];
__device__ float g_h1  [TOK * 512];
__device__ float g_x2  [TOK * Ec];
__device__ float g_ao  [TOK * Ec];
__device__ float g_x3  [TOK * Ec];
__device__ float g_cosT[Nc * HDc];
__device__ float g_sinT[Nc * HDc];
// slot path (collapsed: one row per batch, slots identical across s)
__device__ float g_xbar [Bc * Ec];
__device__ float g_vbar [Bc * FDc];
__device__ float g_slots[Bc * FDc];
__device__ float g_sln  [Bc * FDc];
__device__ float g_gi   [Bc * 3 * FDc];
__device__ float g_gh   [Bc * 3 * FDc];
__device__ float g_m1   [Bc * 2 * FDc];

// ---------------------------------------------------------------------------
// Helpers
// ---------------------------------------------------------------------------
__device__ __forceinline__ float gelu_exact(float x) {
    return 0.5f * x * (1.0f + erff(x * 0.70710678118654752f));
}

__device__ __forceinline__ uint32_t f2tf32(float x) {
    uint32_t r;
    asm("cvt.rna.tf32.f32 %0, %1;" : "=r"(r) : "f"(x));
    return r;
}

__device__ __forceinline__ void mma_tf32(float (&d)[4], const uint32_t (&a)[4],
                                         const uint32_t (&b)[2]) {
    asm volatile(
        "mma.sync.aligned.m16n8k8.row.col.f32.tf32.tf32.f32 "
        "{%0,%1,%2,%3}, {%4,%5,%6,%7}, {%8,%9}, {%0,%1,%2,%3};\n"
        : "+f"(d[0]), "+f"(d[1]), "+f"(d[2]), "+f"(d[3])
        : "r"(a[0]), "r"(a[1]), "r"(a[2]), "r"(a[3]), "r"(b[0]), "r"(b[1]));
}

__device__ __forceinline__ void mma_f16(float (&d)[4], const uint32_t (&a)[4],
                                        const uint32_t (&b)[2]) {
    asm volatile(
        "mma.sync.aligned.m16n8k16.row.col.f32.f16.f16.f32 "
        "{%0,%1,%2,%3}, {%4,%5,%6,%7}, {%8,%9}, {%0,%1,%2,%3};\n"
        : "+f"(d[0]), "+f"(d[1]), "+f"(d[2]), "+f"(d[3])
        : "r"(a[0]), "r"(a[1]), "r"(a[2]), "r"(a[3]), "r"(b[0]), "r"(b[1]));
}

__device__ __forceinline__ uint32_t packh2(float x, float y) {
    __half2 h = __floats2half2_rn(x, y);   // x -> low half (a0/b0 = first k)
    return *(uint32_t*)&h;
}

// ---------------------------------------------------------------------------
// RoPE tables
// ---------------------------------------------------------------------------
__global__ void rope_init_kernel() {
    int n = blockIdx.x;          // 0..255
    int d = threadIdx.x;         // 0..63
    int gy = n >> 4, gx = n & 15;
    int pos = (d < 32) ? gy : gx;
    int dd  = (d < 32) ? d : d - 32;
    float val;
    if (dd < 16) {
        float inv = expf(-9.210340371976184f * (2.0f * dd) / 32.0f);
        val = sinf((float)pos * inv);
    } else {
        float inv = expf(-9.210340371976184f * (2.0f * (dd - 16)) / 32.0f);
        val = cosf((float)pos * inv);
    }
    g_cosT[n * 64 + d] = cosf(val);
    g_sinT[n * 64 + d] = sinf(val);
}

// ---------------------------------------------------------------------------
// Patch / im2col builder: 4 tokens per 256-thread block.
// ---------------------------------------------------------------------------
__global__ __launch_bounds__(256)
void patch_kernel(const float* __restrict__ state, float* __restrict__ P) {
    int bn = blockIdx.x * 4 + (threadIdx.x >> 6);
    int b = bn >> 8, n = bn & 255;
    int gy = n >> 4, gx = n & 15;
    int p = threadIdx.x & 63;          // 0..63
    int py = p >> 3, px = p & 7;
    int y = gy * 8 + py, x = gx * 8 + px;
    const float* sb = state + (size_t)b * Hc * Wc;
    float* row = P + (size_t)bn * 768;
    for (int k = p; k < 768; k += 64) row[k] = 0.f;

    float v[3][3];
    #pragma unroll
    for (int di = 0; di < 3; di++) {
        int yy = min(max(y + di - 1, 0), Hc - 1);
        #pragma unroll
        for (int dj = 0; dj < 3; dj++) {
            int xx = min(max(x + dj - 1, 0), Wc - 1);
            v[di][dj] = sb[yy * Wc + xx];
        }
    }
    float sx = (v[0][2] + 2.f * v[1][2] + v[2][2]) - (v[0][0] + 2.f * v[1][0] + v[2][0]);
    float sy = (v[2][0] + 2.f * v[2][1] + v[2][2]) - (v[0][0] + 2.f * v[0][1] + v[0][2]);
    int id = (int)sb[y * Wc + x];
    __syncthreads();
    row[id * 64 + p]  = 1.f;
    row[640 + p]      = sx;
    row[704 + p]      = sy;
}

// ---------------------------------------------------------------------------
// FP16 tensor-core GEMM: C[M,N] = act(A[M,K] @ W[N,K]^T + bias) (+res).
// BM=128, BN=128, BK=32 floats (16 packed fp16x2 words/row, stride 20).
// 256 threads (8 warps), warp tile m32 x n64 — m16n8k16 fragment addresses
// are identical expressions to the proven tf32 kernel. fp16 mantissa (10b)
// == tf32 mantissa, all operands in range -> accuracy equivalent to tf32.
// M,N multiples of 128; K multiple of 32.
// ---------------------------------------------------------------------------
__global__ __launch_bounds__(256, 2)
void gemm_f16_kernel(const float* __restrict__ A,
                     const float* __restrict__ W,
                     const float* __restrict__ bias, const float* __restrict__ res,
                     float* __restrict__ C,
                     int M, int N, int K, int act) {
    __shared__ uint32_t As[2][128][20];
    __shared__ uint32_t Bs[2][128][20];

    int tid = threadIdx.x;
    int m0 = blockIdx.y * 128, n0 = blockIdx.x * 128;
    int warp = tid >> 5, lane = tid & 31;
    int wm = warp & 3, wn = warp >> 2;   // wm: 4 x 32 rows, wn: 2 x 64 cols
    int q = lane >> 2, t = lane & 3;

    int r    = tid >> 1;                 // 0..127 (row of both A and B tiles)
    int half = tid & 1;                  // which 16-float half of the 32-float row

    const float* Ap = A + (size_t)(m0 + r) * K + half * 16;
    const float* Wp = W + (size_t)(n0 + r) * K + half * 16;

    float acc[2][8][4];
    #pragma unroll
    for (int mt = 0; mt < 2; mt++)
        #pragma unroll
        for (int nt = 0; nt < 8; nt++)
            #pragma unroll
            for (int i = 0; i < 4; i++) acc[mt][nt][i] = 0.f;

    int ntiles = K >> 5;
    float4 a0 = *(const float4*)(Ap + 0);
    float4 a1 = *(const float4*)(Ap + 4);
    float4 a2 = *(const float4*)(Ap + 8);
    float4 a3 = *(const float4*)(Ap + 12);
    float4 b0 = *(const float4*)(Wp + 0);
    float4 b1 = *(const float4*)(Wp + 4);
    float4 b2 = *(const float4*)(Wp + 8);
    float4 b3 = *(const float4*)(Wp + 12);

    int buf = 0;
    for (int kt = 0; kt < ntiles; kt++) {
        // convert + store staged tile
        {
            uint4 u0, u1;
            u0.x = packh2(a0.x, a0.y); u0.y = packh2(a0.z, a0.w);
            u0.z = packh2(a1.x, a1.y); u0.w = packh2(a1.z, a1.w);
            u1.x = packh2(a2.x, a2.y); u1.y = packh2(a2.z, a2.w);
            u1.z = packh2(a3.x, a3.y); u1.w = packh2(a3.z, a3.w);
            *(uint4*)&As[buf][r][half * 8]     = u0;
            *(uint4*)&As[buf][r][half * 8 + 4] = u1;
            u0.x = packh2(b0.x, b0.y); u0.y = packh2(b0.z, b0.w);
            u0.z = packh2(b1.x, b1.y); u0.w = packh2(b1.z, b1.w);
            u1.x = packh2(b2.x, b2.y); u1.y = packh2(b2.z, b2.w);
            u1.z = packh2(b3.x, b3.y); u1.w = packh2(b3.z, b3.w);
            *(uint4*)&Bs[buf][r][half * 8]     = u0;
            *(uint4*)&Bs[buf][r][half * 8 + 4] = u1;
        }
        __syncthreads();

        // prefetch next tile while MMAs run
        if (kt + 1 < ntiles) {
            int off = (kt + 1) * 32;
            a0 = *(const float4*)(Ap + off + 0);
            a1 = *(const float4*)(Ap + off + 4);
            a2 = *(const float4*)(Ap + off + 8);
            a3 = *(const float4*)(Ap + off + 12);
            b0 = *(const float4*)(Wp + off + 0);
            b1 = *(const float4*)(Wp + off + 4);
            b2 = *(const float4*)(Wp + off + 8);
            b3 = *(const float4*)(Wp + off + 12);
        }

        #pragma unroll
        for (int ks = 0; ks < 2; ks++) {
            int kc = ks * 8 + t;
            uint32_t af[2][4], bf[8][2];
            #pragma unroll
            for (int mt = 0; mt < 2; mt++) {
                int rr = wm * 32 + mt * 16 + q;
                af[mt][0] = As[buf][rr][kc];
                af[mt][1] = As[buf][rr + 8][kc];
                af[mt][2] = As[buf][rr][kc + 4];
                af[mt][3] = As[buf][rr + 8][kc + 4];
            }
            #pragma unroll
            for (int nt = 0; nt < 8; nt++) {
                int nn = wn * 64 + nt * 8 + q;
                bf[nt][0] = Bs[buf][nn][kc];
                bf[nt][1] = Bs[buf][nn][kc + 4];
            }
            #pragma unroll
            for (int mt = 0; mt < 2; mt++)
                #pragma unroll
                for (int nt = 0; nt < 8; nt++)
                    mma_f16(acc[mt][nt], af[mt], bf[nt]);
        }
        __syncthreads();
        buf ^= 1;
    }

    #pragma unroll
    for (int mt = 0; mt < 2; mt++) {
        #pragma unroll
        for (int nt = 0; nt < 8; nt++) {
            int gm0 = m0 + wm * 32 + mt * 16 + q;
            int gn  = n0 + wn * 64 + nt * 8 + 2 * t;
            float bb0 = bias ? bias[gn]     : 0.f;
            float bb1 = bias ? bias[gn + 1] : 0.f;
            #pragma unroll
            for (int halfm = 0; halfm < 2; halfm++) {
                int gm = gm0 + halfm * 8;
                float c0 = acc[mt][nt][halfm * 2 + 0] + bb0;
                float c1 = acc[mt][nt][halfm * 2 + 1] + bb1;
                if (act == 1) { c0 = gelu_exact(c0); c1 = gelu_exact(c1); }
                size_t idx = (size_t)gm * N + gn;
                if (res) { c0 += res[idx]; c1 += res[idx + 1]; }
                *(float2*)(C + idx) = make_float2(c0, c1);
            }
        }
    }
}

static inline void gemm_f16(const float* A, const float* W, const float* bias,
                            const float* res, float* C, int M, int N, int K, int act) {
    dim3 grid(N / 128, M / 128);
    gemm_f16_kernel<<<grid, 256>>>(A, W, bias, res, C, M, N, K, act);
}

// ---------------------------------------------------------------------------
// Slot matvec (proven R14): C[64,N] = act(A[64,K] @ W[N,K]^T + bias) (+res).
// ---------------------------------------------------------------------------
__global__ __launch_bounds__(256)
void slot_mv_kernel(const float* __restrict__ A, const float* __restrict__ W,
                    const float* __restrict__ bias, const float* __restrict__ res,
                    float* __restrict__ C, int N, int K, int act) {
    extern __shared__ float Asm[];     // [8][K]
    int jt = blockIdx.x, mt = blockIdx.y;
    int tid = threadIdx.x, warp = tid >> 5, lane = tid & 31;

    for (int i = tid; i < 8 * K; i += 256)
        Asm[i] = A[(size_t)(mt * 8 + i / K) * K + (i % K)];
    __syncthreads();

    int j = jt * 8 + warp;
    const float* wr = W + (size_t)j * K;
    float acc[8] = {};
    for (int k = lane; k < K; k += 32) {
        float wv = wr[k];
        #pragma unroll
        for (int m = 0; m < 8; m++) acc[m] += wv * Asm[m * K + k];
    }
    #pragma unroll
    for (int m = 0; m < 8; m++)
        #pragma unroll
        for (int o = 16; o; o >>= 1)
            acc[m] += __shfl_xor_sync(0xffffffffu, acc[m], o);

    if (lane == 0) {
        float b = bias ? bias[j] : 0.f;
        #pragma unroll
        for (int m = 0; m < 8; m++) {
            float c = acc[m] + b;
            if (act == 1) c = gelu_exact(c);
            size_t idx = (size_t)(mt * 8 + m) * N + j;
            if (res) c += res[idx];
            C[idx] = c;
        }
    }
}

static inline void slot_mv(const float* A, const float* W, const float* bias,
                           const float* res, float* C, int N, int K, int act) {
    dim3 grid(N / 8, 8);
    slot_mv_kernel<<<grid, 256, 8 * K * 4>>>(A, W, bias, res, C, N, K, act);
}

// ---------------------------------------------------------------------------
// LayerNorm: warp per row, single pass, float4.
// ---------------------------------------------------------------------------
__global__ __launch_bounds__(256)
void ln_warp_kernel(const float* __restrict__ x, const float* __restrict__ g,
                    const float* __restrict__ b, float* __restrict__ y, int cols) {
    int row = blockIdx.x * 8 + (threadIdx.x >> 5);
    int lane = threadIdx.x & 31;
    int cols4 = cols >> 2;
    const float4* xr = (const float4*)(x + (size_t)row * cols);
    float s = 0.f, sq = 0.f;
    for (int c = lane; c < cols4; c += 32) {
        float4 v = xr[c];
        s  += (v.x + v.y) + (v.z + v.w);
        sq += v.x * v.x + v.y * v.y + v.z * v.z + v.w * v.w;
    }
    #pragma unroll
    for (int o = 16; o; o >>= 1) {
        s  += __shfl_xor_sync(0xffffffffu, s, o);
        sq += __shfl_xor_sync(0xffffffffu, sq, o);
    }
    float mean = s / (float)cols;
    float var = sq / (float)cols - mean * mean;
    float inv = rsqrtf(fmaxf(var, 0.f) + 1e-5f);
    float4* yr = (float4*)(y + (size_t)row * cols);
    const float4* g4 = (const float4*)g;
    const float4* b4 = (const float4*)b;
    for (int c = lane; c < cols4; c += 32) {
        float4 v = xr[c], gg = g4[c], bb = b4[c], o;
        o.x = (v.x - mean) * inv * gg.x + bb.x;
        o.y = (v.y - mean) * inv * gg.y + bb.y;
        o.z = (v.z - mean) * inv * gg.z + bb.z;
        o.w = (v.w - mean) * inv * gg.w + bb.w;
        yr[c] = o;
    }
}

// ---------------------------------------------------------------------------
// Attention via tf32 MMA, flash-style, RoPE fused (proven R10).
// Ps aliases Qs. Dynamic smem: 3 x 64 x 68 words = 52224 bytes.
// ---------------------------------------------------------------------------
__global__ __launch_bounds__(128)
void attn_mma_kernel(const float* __restrict__ qkv, float* __restrict__ ao) {
    extern __shared__ uint32_t smu[];
    uint32_t (*Qs)[68] = (uint32_t(*)[68])(smu);
    uint32_t (*Ks)[68] = (uint32_t(*)[68])(smu + 64 * 68);
    uint32_t (*Vs)[68] = (uint32_t(*)[68])(smu + 2 * 64 * 68);
    uint32_t (*Ps)[68] = Qs;                 // alias: Q consumed before P written

    int qt = blockIdx.x, h = blockIdx.y, b = blockIdx.z;
    int tid = threadIdx.x;
    int warp = tid >> 5, lane = tid & 31;
    int q = lane >> 2, t = lane & 3;

    const float* base = qkv + (size_t)b * 256 * 768 + h * 64;

    for (int idx = tid; idx < 64 * 16; idx += 128) {
        int r = idx >> 4, c4 = idx & 15;
        int n = qt * 64 + r;
        const float* rp = base + (size_t)n * 768;
        float4 v  = *(const float4*)(rp + c4 * 4);
        float4 cs = *(const float4*)(g_cosT + n * 64 + c4 * 4);
        float4 sn = *(const float4*)(g_sinT + n * 64 + c4 * 4);
        float rot0, rot1, rot2, rot3;
        if (c4 < 8) {
            float4 r0 = *(const float4*)(rp + 8 * c4);
            float4 r1 = *(const float4*)(rp + 8 * c4 + 4);
            rot0 = -r0.y; rot1 = -r0.w; rot2 = -r1.y; rot3 = -r1.w;
        } else {
            float4 r0 = *(const float4*)(rp + 8 * c4 - 64);
            float4 r1 = *(const float4*)(rp + 8 * c4 - 60);
            rot0 = r0.x; rot1 = r0.z; rot2 = r1.x; rot3 = r1.z;
        }
        Qs[r][c4 * 4 + 0] = f2tf32(v.x * cs.x + rot0 * sn.x);
        Qs[r][c4 * 4 + 1] = f2tf32(v.y * cs.y + rot1 * sn.y);
        Qs[r][c4 * 4 + 2] = f2tf32(v.z * cs.z + rot2 * sn.z);
        Qs[r][c4 * 4 + 3] = f2tf32(v.w * cs.w + rot3 * sn.w);
    }
    __syncthreads();

    uint32_t aq[8][4];
    #pragma unroll
    for (int kk = 0; kk < 8; kk++) {
        int rr = warp * 16 + q;
        aq[kk][0] = Qs[rr][8 * kk + t];
        aq[kk][1] = Qs[rr + 8][8 * kk + t];
        aq[kk][2] = Qs[rr][8 * kk + t + 4];
        aq[kk][3] = Qs[rr + 8][8 * kk + t + 4];
    }
    __syncthreads();

    float m0 = -1e30f, m1 = -1e30f, l0 = 0.f, l1 = 0.f;
    float o[8][4];
    #pragma unroll
    for (int nt = 0; nt < 8; nt++)
        #pragma unroll
        for (int i = 0; i < 4; i++) o[nt][i] = 0.f;

    for (int kt = 0; kt < 4; kt++) {
        for (int idx = tid; idx < 64 * 16; idx += 128) {
            int r = idx >> 4, c4 = idx & 15;
            int n = kt * 64 + r;
            const float* rp = base + (size_t)n * 768;
            const float* kp = rp + 256;
            float4 kv = *(const float4*)(kp + c4 * 4);
            float4 vv = *(const float4*)(rp + 512 + c4 * 4);
            float4 cs = *(const float4*)(g_cosT + n * 64 + c4 * 4);
            float4 sn = *(const float4*)(g_sinT + n * 64 + c4 * 4);
            float rot0, rot1, rot2, rot3;
            if (c4 < 8) {
                float4 r0 = *(const float4*)(kp + 8 * c4);
                float4 r1 = *(const float4*)(kp + 8 * c4 + 4);
                rot0 = -r0.y; rot1 = -r0.w; rot2 = -r1.y; rot3 = -r1.w;
            } else {
                float4 r0 = *(const float4*)(kp + 8 * c4 - 64);
                float4 r1 = *(const float4*)(kp + 8 * c4 - 60);
                rot0 = r0.x; rot1 = r0.z; rot2 = r1.x; rot3 = r1.z;
            }
            Ks[r][c4 * 4 + 0] = f2tf32(kv.x * cs.x + rot0 * sn.x);
            Ks[r][c4 * 4 + 1] = f2tf32(kv.y * cs.y + rot1 * sn.y);
            Ks[r][c4 * 4 + 2] = f2tf32(kv.z * cs.z + rot2 * sn.z);
            Ks[r][c4 * 4 + 3] = f2tf32(kv.w * cs.w + rot3 * sn.w);
            Vs[r][c4 * 4 + 0] = f2tf32(vv.x); Vs[r][c4 * 4 + 1] = f2tf32(vv.y);
            Vs[r][c4 * 4 + 2] = f2tf32(vv.z); Vs[r][c4 * 4 + 3] = f2tf32(vv.w);
        }
        __syncthreads();

        float s[8][4];
        #pragma unroll
        for (int nt = 0; nt < 8; nt++)
            #pragma unroll
            for (int i = 0; i < 4; i++) s[nt][i] = 0.f;
        #pragma unroll
        for (int kk = 0; kk < 8; kk++) {
            #pragma unroll
            for (int nt = 0; nt < 8; nt++) {
                uint32_t bf[2] = {Ks[nt * 8 + q][8 * kk + t],
                                  Ks[nt * 8 + q][8 * kk + t + 4]};
                mma_tf32(s[nt], aq[kk], bf);
            }
        }

        float rmax0 = -1e30f, rmax1 = -1e30f;
        #pragma unroll
        for (int nt = 0; nt < 8; nt++) {
            s[nt][0] *= 0.125f; s[nt][1] *= 0.125f;
            s[nt][2] *= 0.125f; s[nt][3] *= 0.125f;
            rmax0 = fmaxf(rmax0, fmaxf(s[nt][0], s[nt][1]));
            rmax1 = fmaxf(rmax1, fmaxf(s[nt][2], s[nt][3]));
        }
        rmax0 = fmaxf(rmax0, __shfl_xor_sync(0xffffffffu, rmax0, 1));
        rmax0 = fmaxf(rmax0, __shfl_xor_sync(0xffffffffu, rmax0, 2));
        rmax1 = fmaxf(rmax1, __shfl_xor_sync(0xffffffffu, rmax1, 1));
        rmax1 = fmaxf(rmax1, __shfl_xor_sync(0xffffffffu, rmax1, 2));
        float nm0 = fmaxf(m0, rmax0), nm1 = fmaxf(m1, rmax1);
        float c0 = __expf(m0 - nm0), c1 = __expf(m1 - nm1);
        m0 = nm0; m1 = nm1;
        float rs0 = 0.f, rs1 = 0.f;
        #pragma unroll
        for (int nt = 0; nt < 8; nt++) {
            s[nt][0] = __expf(s[nt][0] - m0);
            s[nt][1] = __expf(s[nt][1] - m0);
            s[nt][2] = __expf(s[nt][2] - m1);
            s[nt][3] = __expf(s[nt][3] - m1);
            rs0 += s[nt][0] + s[nt][1];
            rs1 += s[nt][2] + s[nt][3];
        }
        rs0 += __shfl_xor_sync(0xffffffffu, rs0, 1);
        rs0 += __shfl_xor_sync(0xffffffffu, rs0, 2);
        rs1 += __shfl_xor_sync(0xffffffffu, rs1, 1);
        rs1 += __shfl_xor_sync(0xffffffffu, rs1, 2);
        l0 = l0 * c0 + rs0;
        l1 = l1 * c1 + rs1;
        #pragma unroll
        for (int nt = 0; nt < 8; nt++) {
            o[nt][0] *= c0; o[nt][1] *= c0;
            o[nt][2] *= c1; o[nt][3] *= c1;
        }

        #pragma unroll
        for (int nt = 0; nt < 8; nt++) {
            int col = nt * 8 + 2 * t;
            Ps[warp * 16 + q][col]         = f2tf32(s[nt][0]);
            Ps[warp * 16 + q][col + 1]     = f2tf32(s[nt][1]);
            Ps[warp * 16 + q + 8][col]     = f2tf32(s[nt][2]);
            Ps[warp * 16 + q + 8][col + 1] = f2tf32(s[nt][3]);
        }
        __syncwarp();

        #pragma unroll
        for (int kk = 0; kk < 8; kk++) {
            uint32_t pa[4];
            pa[0] = Ps[warp * 16 + q][8 * kk + t];
            pa[1] = Ps[warp * 16 + q + 8][8 * kk + t];
            pa[2] = Ps[warp * 16 + q][8 * kk + t + 4];
            pa[3] = Ps[warp * 16 + q + 8][8 * kk + t + 4];
            #pragma unroll
            for (int nt = 0; nt < 8; nt++) {
                uint32_t bf[2] = {Vs[8 * kk + t][8 * nt + q],
                                  Vs[8 * kk + t + 4][8 * nt + q]};
                mma_tf32(o[nt], pa, bf);
            }
        }
        __syncthreads();
    }

    float inv0 = 1.f / l0, inv1 = 1.f / l1;
    int r0 = qt * 64 + warp * 16 + q;
    #pragma unroll
    for (int nt = 0; nt < 8; nt++) {
        int col = h * 64 + nt * 8 + 2 * t;
        float* p0 = ao + ((size_t)b * 256 + r0) * 256 + col;
        float* p1 = ao + ((size_t)b * 256 + r0 + 8) * 256 + col;
        *(float2*)p0 = make_float2(o[nt][0] * inv0, o[nt][1] * inv0);
        *(float2*)p1 = make_float2(o[nt][2] * inv1, o[nt][3] * inv1);
    }
}

// ---------------------------------------------------------------------------
// Collapsed slot path.
// ---------------------------------------------------------------------------
__global__ __launch_bounds__(256)
void colmean_kernel(const float* __restrict__ lnb, float* __restrict__ xbar) {
    int b = blockIdx.x;
    int c = threadIdx.x;
    const float* p = lnb + (size_t)b * 256 * 256 + c;
    float s = 0.f;
    #pragma unroll 8
    for (int n = 0; n < 256; n++) s += p[(size_t)n * 256];
    xbar[b * 256 + c] = s * (1.f / 256.f);
}

__global__ __launch_bounds__(256)
void gru_ln_kernel(const float* __restrict__ gi, const float* __restrict__ gh,
                   const float* __restrict__ bhh,
                   float* __restrict__ slots,
                   const float* __restrict__ nm_g, const float* __restrict__ nm_b,
                   float* __restrict__ sln, int first) {
    int row = blockIdx.x * 8 + (threadIdx.x >> 5);
    int lane = threadIdx.x & 31;
    const float* gir = gi + (size_t)row * 960;
    const float* ghr = first ? bhh : gh + (size_t)row * 960;
    float* sr = slots + (size_t)row * 320;
    float news[10];
    float s = 0.f, sq = 0.f;
    #pragma unroll
    for (int i = 0; i < 10; i++) {
        int f = lane + 32 * i;
        float ir = gir[f], iz = gir[320 + f], in_ = gir[640 + f];
        float hr = ghr[f], hz = ghr[320 + f], hn  = ghr[640 + f];
        float r = 1.f / (1.f + __expf(-(ir + hr)));
        float z = 1.f / (1.f + __expf(-(iz + hz)));
        float nn = tanhf(in_ + r * hn);
        float hprev = first ? 0.f : sr[f];
        float v = (1.f - z) * nn + z * hprev;
        news[i] = v;
        s += v; sq += v * v;
    }
    #pragma unroll
    for (int o = 16; o; o >>= 1) {
        s  += __shfl_xor_sync(0xffffffffu, s, o);
        sq += __shfl_xor_sync(0xffffffffu, sq, o);
    }
    float mean = s / 320.f;
    float var = sq / 320.f - mean * mean;
    float inv = rsqrtf(fmaxf(var, 0.f) + 1e-5f);
    float* lr = sln + (size_t)row * 320;
    #pragma unroll
    for (int i = 0; i < 10; i++) {
        int f = lane + 32 * i;
        sr[f] = news[i];
        lr[f] = (news[i] - mean) * inv * nm_g[f] + nm_b[f];
    }
}

__global__ void output_kernel(const float* __restrict__ slots,
                              float* __restrict__ out) {
    int idx = blockIdx.x * blockDim.x + threadIdx.x;
    const int SLOTS = Bc * NSc * FDc;      // 163840
    const int MASKS = Bc * NSc * Nc;       // 131072
    if (idx < SLOTS) {
        int b = idx / (NSc * FDc);
        int f = idx % FDc;
        out[idx] = slots[b * FDc + f];
    } else if (idx < SLOTS + MASKS) {
        out[idx] = 0.125f;
    }
}

// ---------------------------------------------------------------------------
// Host launcher
// ---------------------------------------------------------------------------
template <typename T>
static float* sym_addr(T& sym) {
    void* p = nullptr;
    cudaGetSymbolAddress(&p, sym);
    return (float*)p;
}

extern "C" void kernel_launch(void* const* d_in, const int* in_sizes, int n_in,
                              void* d_out, int out_size) {
    const float* state    = (const float*)d_in[0];
    const float* conv_w   = (const float*)d_in[1];
    const float* conv_b   = (const float*)d_in[2];
    const float* mlp_ln_g = (const float*)d_in[3];
    const float* mlp_ln_b = (const float*)d_in[4];
    const float* mlp_w1   = (const float*)d_in[5];
    const float* mlp_b1   = (const float*)d_in[6];
    const float* mlp_w2   = (const float*)d_in[7];
    const float* mlp_b2   = (const float*)d_in[8];
    const float* qkv_w    = (const float*)d_in[9];
    const float* qkv_b    = (const float*)d_in[10];
    const float* proj_w   = (const float*)d_in[11];
    const float* proj_b   = (const float*)d_in[12];
    const float* ni_g     = (const float*)d_in[13];
    const float* ni_b     = (const float*)d_in[14];
    const float* nm_g     = (const float*)d_in[17];
    const float* nm_b     = (const float*)d_in[18];
    const float* v_w      = (const float*)d_in[21];
    const float* gru_wih  = (const float*)d_in[22];
    const float* gru_whh  = (const float*)d_in[23];
    const float* gru_bih  = (const float*)d_in[24];
    const float* gru_bhh  = (const float*)d_in[25];
    const float* smlp_w1  = (const float*)d_in[26];
    const float* smlp_b1  = (const float*)d_in[27];
    const float* smlp_w2  = (const float*)d_in[28];
    const float* smlp_b2  = (const float*)d_in[29];
    float* out = (float*)d_out;

    float* P     = sym_addr(g_P);
    float* x0    = sym_addr(g_x0);
    float* lnb   = sym_addr(g_ln);
    float* h1    = sym_addr(g_h1);
    float* x2    = sym_addr(g_x2);
    float* ao    = sym_addr(g_ao);
    float* x3    = sym_addr(g_x3);
    float* xbar  = sym_addr(g_xbar);
    float* vbar  = sym_addr(g_vbar);
    float* slots = sym_addr(g_slots);
    float* sln   = sym_addr(g_sln);
    float* gi    = sym_addr(g_gi);
    float* gh    = sym_addr(g_gh);
    float* m1    = sym_addr(g_m1);

    const int ATTN_SMEM = 3 * 64 * 68 * 4;   // 52224 bytes
    cudaFuncSetAttribute(attn_mma_kernel,
                         cudaFuncAttributeMaxDynamicSharedMemorySize, ATTN_SMEM);

    // 1. RoPE tables + patch matrix
    rope_init_kernel<<<Nc, HDc>>>();
    patch_kernel<<<TOK / 4, 256>>>(state, P);

    // 2. Patch conv as fp16 tensor-core GEMM (one-hot/Sobel entries exact in fp16)
    gemm_f16(P, conv_w, conv_b, nullptr, x0, TOK, 256, 768, 0);

    // 3. Token MLP
    ln_warp_kernel<<<TOK / 8, 256>>>(x0, mlp_ln_g, mlp_ln_b, lnb, 256);
    gemm_f16(lnb, mlp_w1, mlp_b1, nullptr, h1, TOK, 512, 256, 1);
    gemm_f16(h1, mlp_w2, mlp_b2, nullptr, x2, TOK, 256, 512, 0);

    // 4. QKV + attention (RoPE fused) + proj (residual with x2)
    gemm_f16(x2, qkv_w, qkv_b, nullptr, P, TOK, 768, 256, 0);
    attn_mma_kernel<<<dim3(4, HEADSc, Bc), 128, ATTN_SMEM>>>(P, ao);
    gemm_f16(ao, proj_w, proj_b, x2, x3, TOK, 256, 256, 0);

    // 5. Norm + collapsed slot-attention prologue (parallel fp32 matvecs)
    ln_warp_kernel<<<TOK / 8, 256>>>(x3, ni_g, ni_b, lnb, 256);
    colmean_kernel<<<Bc, 256>>>(lnb, xbar);
    slot_mv(xbar, v_w, nullptr, nullptr, vbar, 320, 256, 0);
    slot_mv(vbar, gru_wih, gru_bih, nullptr, gi, 960, 320, 0);

    // 6. Slot iterations (collapsed; it0 skips the gh matvec — gh == bhh exactly)
    for (int it = 0; it < ITc; it++) {
        if (it == 0) {
            gru_ln_kernel<<<Bc / 8, 256>>>(gi, nullptr, gru_bhh, slots,
                                           nm_g, nm_b, sln, 1);
        } else {
            slot_mv(slots, gru_whh, gru_bhh, nullptr, gh, 960, 320, 0);
            gru_ln_kernel<<<Bc / 8, 256>>>(gi, gh, gru_bhh, slots,
                                           nm_g, nm_b, sln, 0);
        }
        slot_mv(sln, smlp_w1, smlp_b1, nullptr, m1, 640, 320, 1);
        slot_mv(m1, smlp_w2, smlp_b2, slots, slots, 320, 640, 0);
    }

    // 7. Pack outputs
    int total = Bc * NSc * FDc + Bc * NSc * Nc;
    output_kernel<<<(total + 255) / 256, 256>>>(slots, out);
}